// round 2
// baseline (speedup 1.0000x reference)
#include <cuda_runtime.h>
#include <math.h>

// Problem dims
#define VV   50257
#define SS   1024
#define BBAT 2
#define DM   768
#define NH   12
#define HDIM 64
#define FF   3072
#define NL   2
#define MTOK (BBAT*SS)   // 2048

// ---------------- scratch (device globals; no cudaMalloc allowed) ----------
__device__ float g_x  [MTOK*DM];
__device__ float g_h  [MTOK*DM];
__device__ float g_q  [MTOK*DM];
__device__ float g_k  [MTOK*DM];
__device__ float g_v  [MTOK*DM];
__device__ float g_att[MTOK*DM];
__device__ float g_ffn[MTOK*FF];

// ---------------- embed: x = tok_emb[idx] + pos_emb ------------------------
__global__ void embed_k(const int* __restrict__ idx,
                        const float* __restrict__ tok,
                        const float* __restrict__ pos) {
    int i = blockIdx.x * blockDim.x + threadIdx.x;
    if (i >= MTOK * DM) return;
    int m = i / DM, d = i % DM;
    int s = m % SS;
    int w = idx[m];
    g_x[i] = tok[(long)w * DM + d] + pos[s * DM + d];
}

// ---------------- layernorm (row per block) --------------------------------
__global__ void ln_k(const float* __restrict__ in, float* __restrict__ out,
                     const float* __restrict__ w, const float* __restrict__ b) {
    int row = blockIdx.x;
    const float* x = in + (long)row * DM;
    int tid = threadIdx.x;
    float s = 0.f, s2 = 0.f;
    for (int d = tid; d < DM; d += blockDim.x) {
        float v = x[d]; s += v; s2 += v * v;
    }
    // block reduce (256 threads = 8 warps)
    __shared__ float rs[8], rs2[8], bc[2];
    for (int o = 16; o > 0; o >>= 1) {
        s  += __shfl_xor_sync(0xffffffffu, s,  o);
        s2 += __shfl_xor_sync(0xffffffffu, s2, o);
    }
    if ((tid & 31) == 0) { rs[tid >> 5] = s; rs2[tid >> 5] = s2; }
    __syncthreads();
    if (tid == 0) {
        float a = 0.f, a2 = 0.f;
        for (int i = 0; i < 8; i++) { a += rs[i]; a2 += rs2[i]; }
        float mean = a / DM;
        float var  = a2 / DM - mean * mean;
        bc[0] = mean; bc[1] = rsqrtf(var + 1e-5f);
    }
    __syncthreads();
    float mean = bc[0], inv = bc[1];
    for (int d = tid; d < DM; d += blockDim.x)
        out[(long)row * DM + d] = (x[d] - mean) * inv * w[d] + b[d];
}

// ---------------- GEMM: C[M,N] = A[M,K] @ B (+bias, epilogue) --------------
// BT=0: B is [K,N] row-major.  BT=1: B is [N,K] row-major (B transposed).
// EPI: 0 = bias only, 1 = bias+gelu, 2 = bias + residual add (res[M,N]).
__device__ __forceinline__ float gelu_f(float z) {
    float z3 = z * z * z;
    return 0.5f * z * (1.0f + tanhf(0.7978845608028654f * (z + 0.044715f * z3)));
}

template <int BT, int EPI>
__global__ __launch_bounds__(256)
void gemm_k(const float* __restrict__ A, const float* __restrict__ Bm,
            const float* __restrict__ bias, const float* __restrict__ res,
            float* __restrict__ C, int Mdim, int Ndim, int Kdim) {
    const int BK = 16;
    __shared__ float As[BK][132];
    __shared__ float Bs[BK][132];

    int tx = threadIdx.x, ty = threadIdx.y;
    int tid = ty * 16 + tx;
    int a0 = blockIdx.y * 128;
    int b0 = blockIdx.x * 128;

    float acc[8][8];
#pragma unroll
    for (int i = 0; i < 8; i++)
#pragma unroll
        for (int j = 0; j < 8; j++) acc[i][j] = 0.f;

    for (int k0 = 0; k0 < Kdim; k0 += BK) {
        // A tile: 128 rows x 16 cols -> As[c][r]  (M always multiple of 128)
#pragma unroll
        for (int i = 0; i < 8; i++) {
            int e = tid + i * 256;
            int r = e >> 4, c = e & 15;
            As[c][r] = A[(long)(a0 + r) * Kdim + (k0 + c)];
        }
        if (BT == 0) {
            // B tile: 16 rows x 128 cols -> Bs[kk][n]
#pragma unroll
            for (int i = 0; i < 8; i++) {
                int e = tid + i * 256;
                int kk = e >> 7, n = e & 127;
                int col = b0 + n;
                Bs[kk][n] = (col < Ndim) ? Bm[(long)(k0 + kk) * Ndim + col] : 0.f;
            }
        } else {
            // Bt tile: 128 rows x 16 cols -> Bs[c][n]
#pragma unroll
            for (int i = 0; i < 8; i++) {
                int e = tid + i * 256;
                int n = e >> 4, c = e & 15;
                int row = b0 + n;
                Bs[c][n] = (row < Ndim) ? Bm[(long)row * Kdim + (k0 + c)] : 0.f;
            }
        }
        __syncthreads();

#pragma unroll
        for (int kk = 0; kk < BK; kk++) {
            float4 av0 = *(const float4*)&As[kk][ty * 8];
            float4 av1 = *(const float4*)&As[kk][ty * 8 + 4];
            float4 bv0 = *(const float4*)&Bs[kk][tx * 8];
            float4 bv1 = *(const float4*)&Bs[kk][tx * 8 + 4];
            float ar[8] = {av0.x, av0.y, av0.z, av0.w, av1.x, av1.y, av1.z, av1.w};
            float br[8] = {bv0.x, bv0.y, bv0.z, bv0.w, bv1.x, bv1.y, bv1.z, bv1.w};
#pragma unroll
            for (int i = 0; i < 8; i++)
#pragma unroll
                for (int j = 0; j < 8; j++) acc[i][j] += ar[i] * br[j];
        }
        __syncthreads();
    }

    // epilogue
    const bool vec_ok = ((Ndim & 3) == 0);   // row stride must keep float4 alignment
#pragma unroll
    for (int i = 0; i < 8; i++) {
        long row = a0 + ty * 8 + i;
#pragma unroll
        for (int jj = 0; jj < 2; jj++) {
            int colb = b0 + tx * 8 + jj * 4;
            float v[4];
#pragma unroll
            for (int j = 0; j < 4; j++) {
                float c = acc[i][jj * 4 + j];
                int col = colb + j;
                if (col < Ndim) {
                    if (bias) c += bias[col];
                    if (EPI == 1) c = gelu_f(c);
                    if (EPI == 2) c += res[row * Ndim + col];
                }
                v[j] = c;
            }
            if (vec_ok && colb + 3 < Ndim) {
                *(float4*)&C[row * Ndim + colb] = make_float4(v[0], v[1], v[2], v[3]);
            } else {
#pragma unroll
                for (int j = 0; j < 4; j++)
                    if (colb + j < Ndim) C[row * Ndim + colb + j] = v[j];
            }
        }
    }
}

// ---------------- causal attention: one block per (q, h, b) ----------------
__global__ __launch_bounds__(128)
void attn_k() {
    int q = blockIdx.x, h = blockIdx.y, b = blockIdx.z;
    int tid = threadIdx.x;
    int m0 = b * SS;

    __shared__ float qs[HDIM];
    __shared__ float sc[SS];
    __shared__ float rbuf[5];
    __shared__ float part[128];

    const float* qp = g_q + (long)(m0 + q) * DM + h * HDIM;
    if (tid < HDIM) qs[tid] = qp[tid];
    __syncthreads();

    int nk = q + 1;
    float lmax = -1e30f;
    for (int j = tid; j < nk; j += 128) {
        const float4* kp = (const float4*)(g_k + (long)(m0 + j) * DM + h * HDIM);
        float s = 0.f;
#pragma unroll
        for (int d4 = 0; d4 < HDIM / 4; d4++) {
            float4 kv = kp[d4];
            s += qs[d4 * 4 + 0] * kv.x + qs[d4 * 4 + 1] * kv.y
               + qs[d4 * 4 + 2] * kv.z + qs[d4 * 4 + 3] * kv.w;
        }
        s *= 0.125f;           // 1/sqrt(64)
        sc[j] = s;
        lmax = fmaxf(lmax, s);
    }
    // block max
    for (int o = 16; o > 0; o >>= 1) lmax = fmaxf(lmax, __shfl_xor_sync(0xffffffffu, lmax, o));
    if ((tid & 31) == 0) rbuf[tid >> 5] = lmax;
    __syncthreads();
    if (tid == 0) {
        float m = fmaxf(fmaxf(rbuf[0], rbuf[1]), fmaxf(rbuf[2], rbuf[3]));
        rbuf[4] = m;
    }
    __syncthreads();
    float smax = rbuf[4];
    __syncthreads();

    float lsum = 0.f;
    for (int j = tid; j < nk; j += 128) {
        float e = __expf(sc[j] - smax);
        sc[j] = e;
        lsum += e;
    }
    for (int o = 16; o > 0; o >>= 1) lsum += __shfl_xor_sync(0xffffffffu, lsum, o);
    if ((tid & 31) == 0) rbuf[tid >> 5] = lsum;
    __syncthreads();
    if (tid == 0) rbuf[4] = 1.0f / (rbuf[0] + rbuf[1] + rbuf[2] + rbuf[3]);
    __syncthreads();
    float inv = rbuf[4];

    // out[d] = inv * sum_j sc[j] * v[j][d]
    int d = tid & 63, half = tid >> 6;
    float acc = 0.f;
    for (int j = half; j < nk; j += 2)
        acc += sc[j] * g_v[(long)(m0 + j) * DM + h * HDIM + d];
    part[tid] = acc;
    __syncthreads();
    if (tid < 64)
        g_att[(long)(m0 + q) * DM + h * HDIM + tid] = (part[tid] + part[tid + 64]) * inv;
}

// ---------------- host orchestration ---------------------------------------
extern "C" void kernel_launch(void* const* d_in, const int* in_sizes, int n_in,
                              void* d_out, int out_size) {
    const int*   word_idx = (const int*)  d_in[0];
    const float* tok_emb  = (const float*)d_in[1];
    const float* pos_emb  = (const float*)d_in[2];
    const float* ln1_w    = (const float*)d_in[3];
    const float* ln1_b    = (const float*)d_in[4];
    const float* wq       = (const float*)d_in[5];
    const float* bq       = (const float*)d_in[6];
    const float* wk       = (const float*)d_in[7];
    const float* bk       = (const float*)d_in[8];
    const float* wv       = (const float*)d_in[9];
    const float* bv       = (const float*)d_in[10];
    const float* wo       = (const float*)d_in[11];
    const float* bo       = (const float*)d_in[12];
    const float* ln2_w    = (const float*)d_in[13];
    const float* ln2_b    = (const float*)d_in[14];
    const float* w1       = (const float*)d_in[15];
    const float* b1       = (const float*)d_in[16];
    const float* w2       = (const float*)d_in[17];
    const float* b2       = (const float*)d_in[18];
    const float* lnf_w    = (const float*)d_in[19];
    const float* lnf_b    = (const float*)d_in[20];
    float* out = (float*)d_out;

    float *gx, *gh, *gq, *gk, *gv, *ga, *gf;
    cudaGetSymbolAddress((void**)&gx, g_x);
    cudaGetSymbolAddress((void**)&gh, g_h);
    cudaGetSymbolAddress((void**)&gq, g_q);
    cudaGetSymbolAddress((void**)&gk, g_k);
    cudaGetSymbolAddress((void**)&gv, g_v);
    cudaGetSymbolAddress((void**)&ga, g_att);
    cudaGetSymbolAddress((void**)&gf, g_ffn);

    dim3 blk(16, 16);
    dim3 grdD((DM + 127) / 128, MTOK / 128);
    dim3 grdF((FF + 127) / 128, MTOK / 128);
    dim3 grdV((VV + 127) / 128, MTOK / 128);

    embed_k<<<(MTOK * DM + 255) / 256, 256>>>(word_idx, tok_emb, pos_emb);

    for (int l = 0; l < NL; l++) {
        const float* Wq = wq + (long)l * DM * DM;
        const float* Wk = wk + (long)l * DM * DM;
        const float* Wv = wv + (long)l * DM * DM;
        const float* Wo = wo + (long)l * DM * DM;
        const float* W1 = w1 + (long)l * DM * FF;
        const float* W2 = w2 + (long)l * FF * DM;

        ln_k<<<MTOK, 256>>>(gx, gh, ln1_w + l * DM, ln1_b + l * DM);
        gemm_k<0, 0><<<grdD, blk>>>(gh, Wq, bq + l * DM, nullptr, gq, MTOK, DM, DM);
        gemm_k<0, 0><<<grdD, blk>>>(gh, Wk, bk + l * DM, nullptr, gk, MTOK, DM, DM);
        gemm_k<0, 0><<<grdD, blk>>>(gh, Wv, bv + l * DM, nullptr, gv, MTOK, DM, DM);
        attn_k<<<dim3(SS, NH, BBAT), 128>>>();
        gemm_k<0, 2><<<grdD, blk>>>(ga, Wo, bo + l * DM, gx, gx, MTOK, DM, DM);
        ln_k<<<MTOK, 256>>>(gx, gh, ln2_w + l * DM, ln2_b + l * DM);
        gemm_k<0, 1><<<grdF, blk>>>(gh, W1, b1 + l * FF, nullptr, gf, MTOK, FF, DM);
        gemm_k<0, 2><<<grdD, blk>>>(gf, W2, b2 + l * DM, gx, gx, MTOK, DM, FF);
    }

    ln_k<<<MTOK, 256>>>(gx, gh, lnf_w, lnf_b);
    // LM head: logits = h @ tok_emb^T   (tok_emb is [V,D] row-major -> BT=1)
    gemm_k<1, 0><<<grdV, blk>>>(gh, tok_emb, nullptr, nullptr, out, MTOK, VV, DM);
}

// round 4
// speedup vs baseline: 1.3851x; 1.3851x over previous
#include <cuda_runtime.h>
#include <cuda_bf16.h>
#include <cstdint>
#include <math.h>

// Problem dims
#define VV   50257
#define SS   1024
#define BBAT 2
#define DM   768
#define NH   12
#define HDIM 64
#define FF   3072
#define NL   2
#define MTOK (BBAT*SS)   // 2048

// ---------------- scratch (device globals; no cudaMalloc allowed) ----------
__device__ float g_x  [MTOK*DM];
__device__ float g_h  [MTOK*DM];
__device__ float g_q  [MTOK*DM];
__device__ float g_k  [MTOK*DM];
__device__ float g_v  [MTOK*DM];
__device__ float g_att[MTOK*DM];
__device__ float g_ffn[MTOK*FF];

// ---------------- embed ----------------------------------------------------
__global__ void embed_k(const int* __restrict__ idx,
                        const float* __restrict__ tok,
                        const float* __restrict__ pos) {
    int i = blockIdx.x * blockDim.x + threadIdx.x;
    if (i >= MTOK * DM) return;
    int m = i / DM, d = i % DM;
    int s = m % SS;
    int w = idx[m];
    g_x[i] = tok[(long)w * DM + d] + pos[s * DM + d];
}

// ---------------- layernorm -------------------------------------------------
__global__ void ln_k(const float* __restrict__ in, float* __restrict__ out,
                     const float* __restrict__ w, const float* __restrict__ b) {
    int row = blockIdx.x;
    const float* x = in + (long)row * DM;
    int tid = threadIdx.x;
    float s = 0.f, s2 = 0.f;
    for (int d = tid; d < DM; d += blockDim.x) {
        float v = x[d]; s += v; s2 += v * v;
    }
    __shared__ float rs[8], rs2[8], bc[2];
    for (int o = 16; o > 0; o >>= 1) {
        s  += __shfl_xor_sync(0xffffffffu, s,  o);
        s2 += __shfl_xor_sync(0xffffffffu, s2, o);
    }
    if ((tid & 31) == 0) { rs[tid >> 5] = s; rs2[tid >> 5] = s2; }
    __syncthreads();
    if (tid == 0) {
        float a = 0.f, a2 = 0.f;
        for (int i = 0; i < 8; i++) { a += rs[i]; a2 += rs2[i]; }
        float mean = a / DM;
        float var  = a2 / DM - mean * mean;
        bc[0] = mean; bc[1] = rsqrtf(var + 1e-5f);
    }
    __syncthreads();
    float mean = bc[0], inv = bc[1];
    for (int d = tid; d < DM; d += blockDim.x)
        out[(long)row * DM + d] = (x[d] - mean) * inv * w[d] + b[d];
}

// ---------------- tensor-core GEMM (bf16 hi/lo split, fp32 accum) ----------
// C[M,N] = A[M,K] @ B (+bias, epilogue)
// BT=0: B is [K,N] row-major.  BT=1: B is [N,K] row-major.
// EPI: 0 = bias only, 1 = bias+gelu, 2 = bias + residual add.
__device__ __forceinline__ float gelu_f(float z) {
    float z3 = z * z * z;
    return 0.5f * z * (1.0f + tanhf(0.7978845608028654f * (z + 0.044715f * z3)));
}

__device__ __forceinline__ void split_bf(float v, __nv_bfloat16& h, __nv_bfloat16& l) {
    h = __float2bfloat16_rn(v);
    l = __float2bfloat16_rn(v - __bfloat162float(h));
}

__device__ __forceinline__ void ldsm_x4(uint32_t* r, const void* p) {
    uint32_t a = (uint32_t)__cvta_generic_to_shared(p);
    asm volatile("ldmatrix.sync.aligned.m8n8.x4.shared.b16 {%0,%1,%2,%3}, [%4];"
                 : "=r"(r[0]), "=r"(r[1]), "=r"(r[2]), "=r"(r[3]) : "r"(a));
}
__device__ __forceinline__ void ldsm_x2_t(uint32_t* r, const void* p) {
    uint32_t a = (uint32_t)__cvta_generic_to_shared(p);
    asm volatile("ldmatrix.sync.aligned.m8n8.x2.trans.shared.b16 {%0,%1}, [%2];"
                 : "=r"(r[0]), "=r"(r[1]) : "r"(a));
}
__device__ __forceinline__ void mma_bf16(float* c, const uint32_t* a, const uint32_t* b) {
    asm volatile(
        "mma.sync.aligned.m16n8k16.row.col.f32.bf16.bf16.f32 "
        "{%0,%1,%2,%3}, {%4,%5,%6,%7}, {%8,%9}, {%0,%1,%2,%3};"
        : "+f"(c[0]), "+f"(c[1]), "+f"(c[2]), "+f"(c[3])
        : "r"(a[0]), "r"(a[1]), "r"(a[2]), "r"(a[3]), "r"(b[0]), "r"(b[1]));
}

#define ASTR 40    // A smem row stride in bf16 (80B, conflict-free for ldmatrix)
#define BSTR 136   // B smem row stride in bf16 (272B)

template <int BT, int EPI>
__global__ __launch_bounds__(256)
void gemm_mma(const float* __restrict__ A, const float* __restrict__ Bm,
              const float* __restrict__ bias, const float* __restrict__ res,
              float* __restrict__ C, int Mdim, int Ndim, int Kdim) {
    __shared__ __nv_bfloat16 Ah[128][ASTR], Al[128][ASTR];
    __shared__ __nv_bfloat16 Bh[32][BSTR],  Bl[32][BSTR];

    const int tid  = threadIdx.x;
    const int lane = tid & 31;
    const int wid  = tid >> 5;          // 8 warps: 2 (m) x 4 (n)
    const int wm   = (wid >> 2) * 64;   // warp row offset in block tile
    const int wn   = (wid & 3) * 32;    // warp col offset
    const int a0   = blockIdx.y * 128;
    const int b0   = blockIdx.x * 128;

    float acc[4][4][4];
#pragma unroll
    for (int i = 0; i < 4; i++)
#pragma unroll
        for (int j = 0; j < 4; j++)
#pragma unroll
            for (int e = 0; e < 4; e++) acc[i][j][e] = 0.f;

    for (int k0 = 0; k0 < Kdim; k0 += 32) {
        // ---- A tile 128x32 fp32 -> hi/lo bf16 (rows always valid) ----
#pragma unroll
        for (int it = 0; it < 4; it++) {
            int e = tid + it * 256;          // 1024 float4 slots
            int r = e >> 3, c4 = (e & 7) * 4;
            float4 v = *(const float4*)&A[(long)(a0 + r) * Kdim + k0 + c4];
            float vv[4] = {v.x, v.y, v.z, v.w};
#pragma unroll
            for (int j = 0; j < 4; j++) {
                __nv_bfloat16 hh, ll; split_bf(vv[j], hh, ll);
                Ah[r][c4 + j] = hh; Al[r][c4 + j] = ll;
            }
        }
        // ---- B tile -> Bs[k][n] hi/lo ----
        if (BT == 0) {
#pragma unroll
            for (int it = 0; it < 4; it++) {
                int e = tid + it * 256;
                int kk = e >> 5, n4 = (e & 31) * 4;
                int col = b0 + n4;
                float vv[4] = {0.f, 0.f, 0.f, 0.f};
                if (col + 3 < Ndim) {
                    float4 v = *(const float4*)&Bm[(long)(k0 + kk) * Ndim + col];
                    vv[0] = v.x; vv[1] = v.y; vv[2] = v.z; vv[3] = v.w;
                } else {
#pragma unroll
                    for (int j = 0; j < 4; j++)
                        if (col + j < Ndim) vv[j] = Bm[(long)(k0 + kk) * Ndim + col + j];
                }
#pragma unroll
                for (int j = 0; j < 4; j++) {
                    __nv_bfloat16 hh, ll; split_bf(vv[j], hh, ll);
                    Bh[kk][n4 + j] = hh; Bl[kk][n4 + j] = ll;
                }
            }
        } else {
            // B[N,K]: gather 128 n-rows x 32 k, transpose into Bs[k][n]
#pragma unroll
            for (int it = 0; it < 4; it++) {
                int e = tid + it * 256;
                int r = e >> 3, c4 = (e & 7) * 4;
                int nrow = b0 + r;
                float vv[4] = {0.f, 0.f, 0.f, 0.f};
                if (nrow < Ndim) {
                    float4 v = *(const float4*)&Bm[(long)nrow * Kdim + k0 + c4];
                    vv[0] = v.x; vv[1] = v.y; vv[2] = v.z; vv[3] = v.w;
                }
#pragma unroll
                for (int j = 0; j < 4; j++) {
                    __nv_bfloat16 hh, ll; split_bf(vv[j], hh, ll);
                    Bh[c4 + j][r] = hh; Bl[c4 + j][r] = ll;
                }
            }
        }
        __syncthreads();

        // ---- MMA: 2 k-steps of 16 ----
#pragma unroll
        for (int ks = 0; ks < 2; ks++) {
            uint32_t ah[4][4], al[4][4], bh[4][2], bl[4][2];
            int arow = wm + (lane & 15);
            int acol = ks * 16 + (lane >> 4) * 8;
#pragma unroll
            for (int mt = 0; mt < 4; mt++) {
                ldsm_x4(ah[mt], &Ah[arow + mt * 16][acol]);
                ldsm_x4(al[mt], &Al[arow + mt * 16][acol]);
            }
            int brow = ks * 16 + (lane & 15);
#pragma unroll
            for (int nt = 0; nt < 4; nt++) {
                ldsm_x2_t(bh[nt], &Bh[brow][wn + nt * 8]);
                ldsm_x2_t(bl[nt], &Bl[brow][wn + nt * 8]);
            }
#pragma unroll
            for (int mt = 0; mt < 4; mt++)
#pragma unroll
                for (int nt = 0; nt < 4; nt++) {
                    mma_bf16(acc[mt][nt], ah[mt], bh[nt]);
                    mma_bf16(acc[mt][nt], al[mt], bh[nt]);
                    mma_bf16(acc[mt][nt], ah[mt], bl[nt]);
                }
        }
        __syncthreads();
    }

    // ---- epilogue ----
#pragma unroll
    for (int mt = 0; mt < 4; mt++) {
        long r0 = a0 + wm + mt * 16 + (lane >> 2);
        long r1 = r0 + 8;
#pragma unroll
        for (int nt = 0; nt < 4; nt++) {
            int cb = b0 + wn + nt * 8 + (lane & 3) * 2;
#pragma unroll
            for (int j = 0; j < 2; j++) {
                int col = cb + j;
                if (col >= Ndim) continue;
                float v0 = acc[mt][nt][j];       // (r0, col)
                float v1 = acc[mt][nt][2 + j];   // (r1, col)
                if (bias) { v0 += bias[col]; v1 += bias[col]; }
                if (EPI == 1) { v0 = gelu_f(v0); v1 = gelu_f(v1); }
                if (EPI == 2) {
                    v0 += res[r0 * Ndim + col];
                    v1 += res[r1 * Ndim + col];
                }
                C[r0 * Ndim + col] = v0;
                C[r1 * Ndim + col] = v1;
            }
        }
    }
}

// ---------------- causal attention: one block per (q, h, b) ----------------
__global__ __launch_bounds__(128)
void attn_k() {
    int q = blockIdx.x, h = blockIdx.y, b = blockIdx.z;
    int tid = threadIdx.x;
    int m0 = b * SS;

    __shared__ float qs[HDIM];
    __shared__ float sc[SS];
    __shared__ float rbuf[5];
    __shared__ float part[128];

    const float* qp = g_q + (long)(m0 + q) * DM + h * HDIM;
    if (tid < HDIM) qs[tid] = qp[tid];
    __syncthreads();

    int nk = q + 1;
    float lmax = -1e30f;
    for (int j = tid; j < nk; j += 128) {
        const float4* kp = (const float4*)(g_k + (long)(m0 + j) * DM + h * HDIM);
        float s = 0.f;
#pragma unroll
        for (int d4 = 0; d4 < HDIM / 4; d4++) {
            float4 kv = kp[d4];
            s += qs[d4 * 4 + 0] * kv.x + qs[d4 * 4 + 1] * kv.y
               + qs[d4 * 4 + 2] * kv.z + qs[d4 * 4 + 3] * kv.w;
        }
        s *= 0.125f;
        sc[j] = s;
        lmax = fmaxf(lmax, s);
    }
    for (int o = 16; o > 0; o >>= 1) lmax = fmaxf(lmax, __shfl_xor_sync(0xffffffffu, lmax, o));
    if ((tid & 31) == 0) rbuf[tid >> 5] = lmax;
    __syncthreads();
    if (tid == 0) {
        float m = fmaxf(fmaxf(rbuf[0], rbuf[1]), fmaxf(rbuf[2], rbuf[3]));
        rbuf[4] = m;
    }
    __syncthreads();
    float smax = rbuf[4];
    __syncthreads();

    float lsum = 0.f;
    for (int j = tid; j < nk; j += 128) {
        float e = __expf(sc[j] - smax);
        sc[j] = e;
        lsum += e;
    }
    for (int o = 16; o > 0; o >>= 1) lsum += __shfl_xor_sync(0xffffffffu, lsum, o);
    if ((tid & 31) == 0) rbuf[tid >> 5] = lsum;
    __syncthreads();
    if (tid == 0) rbuf[4] = 1.0f / (rbuf[0] + rbuf[1] + rbuf[2] + rbuf[3]);
    __syncthreads();
    float inv = rbuf[4];

    int d = tid & 63;
    int hv = tid >> 6;                     // renamed: `half` is a type once cuda_fp16.h is in
    float acc = 0.f;
    for (int j = hv; j < nk; j += 2)
        acc += sc[j] * g_v[(long)(m0 + j) * DM + h * HDIM + d];
    part[tid] = acc;
    __syncthreads();
    if (tid < 64)
        g_att[(long)(m0 + q) * DM + h * HDIM + tid] = (part[tid] + part[tid + 64]) * inv;
}

// ---------------- host orchestration ---------------------------------------
extern "C" void kernel_launch(void* const* d_in, const int* in_sizes, int n_in,
                              void* d_out, int out_size) {
    const int*   word_idx = (const int*)  d_in[0];
    const float* tok_emb  = (const float*)d_in[1];
    const float* pos_emb  = (const float*)d_in[2];
    const float* ln1_w    = (const float*)d_in[3];
    const float* ln1_b    = (const float*)d_in[4];
    const float* wq       = (const float*)d_in[5];
    const float* bq       = (const float*)d_in[6];
    const float* wk       = (const float*)d_in[7];
    const float* bk       = (const float*)d_in[8];
    const float* wv       = (const float*)d_in[9];
    const float* bv       = (const float*)d_in[10];
    const float* wo       = (const float*)d_in[11];
    const float* bo       = (const float*)d_in[12];
    const float* ln2_w    = (const float*)d_in[13];
    const float* ln2_b    = (const float*)d_in[14];
    const float* w1       = (const float*)d_in[15];
    const float* b1       = (const float*)d_in[16];
    const float* w2       = (const float*)d_in[17];
    const float* b2       = (const float*)d_in[18];
    const float* lnf_w    = (const float*)d_in[19];
    const float* lnf_b    = (const float*)d_in[20];
    float* out = (float*)d_out;

    float *gx, *gh, *gq, *gk, *gv, *ga, *gf;
    cudaGetSymbolAddress((void**)&gx, g_x);
    cudaGetSymbolAddress((void**)&gh, g_h);
    cudaGetSymbolAddress((void**)&gq, g_q);
    cudaGetSymbolAddress((void**)&gk, g_k);
    cudaGetSymbolAddress((void**)&gv, g_v);
    cudaGetSymbolAddress((void**)&ga, g_att);
    cudaGetSymbolAddress((void**)&gf, g_ffn);

    dim3 grdD((DM + 127) / 128, MTOK / 128);
    dim3 grdF((FF + 127) / 128, MTOK / 128);
    dim3 grdV((VV + 127) / 128, MTOK / 128);

    embed_k<<<(MTOK * DM + 255) / 256, 256>>>(word_idx, tok_emb, pos_emb);

    for (int l = 0; l < NL; l++) {
        const float* Wq = wq + (long)l * DM * DM;
        const float* Wk = wk + (long)l * DM * DM;
        const float* Wv = wv + (long)l * DM * DM;
        const float* Wo = wo + (long)l * DM * DM;
        const float* W1 = w1 + (long)l * DM * FF;
        const float* W2 = w2 + (long)l * FF * DM;

        ln_k<<<MTOK, 256>>>(gx, gh, ln1_w + l * DM, ln1_b + l * DM);
        gemm_mma<0, 0><<<grdD, 256>>>(gh, Wq, bq + l * DM, nullptr, gq, MTOK, DM, DM);
        gemm_mma<0, 0><<<grdD, 256>>>(gh, Wk, bk + l * DM, nullptr, gk, MTOK, DM, DM);
        gemm_mma<0, 0><<<grdD, 256>>>(gh, Wv, bv + l * DM, nullptr, gv, MTOK, DM, DM);
        attn_k<<<dim3(SS, NH, BBAT), 128>>>();
        gemm_mma<0, 2><<<grdD, 256>>>(ga, Wo, bo + l * DM, gx, gx, MTOK, DM, DM);
        ln_k<<<MTOK, 256>>>(gx, gh, ln2_w + l * DM, ln2_b + l * DM);
        gemm_mma<0, 1><<<grdF, 256>>>(gh, W1, b1 + l * FF, nullptr, gf, MTOK, FF, DM);
        gemm_mma<0, 2><<<grdD, 256>>>(gf, W2, b2 + l * DM, gx, gx, MTOK, DM, FF);
    }

    ln_k<<<MTOK, 256>>>(gx, gh, lnf_w, lnf_b);
    // LM head: logits = h @ tok_emb^T  (tok_emb [V,D] row-major -> BT=1)
    gemm_mma<1, 0><<<grdV, 256>>>(gh, tok_emb, nullptr, nullptr, out, MTOK, VV, DM);
}

// round 5
// speedup vs baseline: 2.0252x; 1.4622x over previous
#include <cuda_runtime.h>
#include <cuda_bf16.h>
#include <cstdint>
#include <math.h>

#define VV   50257
#define VP   50304            // V padded to multiple of 128
#define SS   1024
#define BBAT 2
#define DM   768
#define NH   12
#define HDIM 64
#define FF   3072
#define NL   2
#define MTOK (BBAT*SS)        // 2048
#define D3   (3*DM)           // 2304

typedef __nv_bfloat16 bf16;

// ---------------- persistent scratch (device globals) ----------------------
__device__ float g_x   [MTOK*DM];
__device__ float g_qkv [MTOK*D3];
__device__ bf16  g_hh  [MTOK*DM],  g_hl[MTOK*DM];
__device__ bf16  g_ah  [MTOK*DM],  g_al[MTOK*DM];
__device__ bf16  g_fh  [MTOK*FF],  g_fl[MTOK*FF];
__device__ bf16  w_qkvh[NL*DM*D3], w_qkvl[NL*DM*D3];
__device__ bf16  w_oh  [NL*DM*DM], w_ol [NL*DM*DM];
__device__ bf16  w_1h  [NL*DM*FF], w_1l [NL*DM*FF];
__device__ bf16  w_2h  [NL*FF*DM], w_2l [NL*FF*DM];
__device__ bf16  g_teh [DM*VP],    g_tel[DM*VP];
__device__ float g_bqkv[NL*D3];

__device__ __forceinline__ void split_bf(float v, bf16& h, bf16& l) {
    h = __float2bfloat16_rn(v);
    l = __float2bfloat16_rn(v - __bfloat162float(h));
}
__device__ __forceinline__ float gelu_f(float z) {
    float z3 = z * z * z;
    return 0.5f * z * (1.0f + tanhf(0.7978845608028654f * (z + 0.044715f * z3)));
}

// ---------------- conversion kernels ---------------------------------------
__global__ void conv_split_k(const float* __restrict__ in, bf16* __restrict__ oh,
                             bf16* __restrict__ ol, int n) {
    int i = blockIdx.x * blockDim.x + threadIdx.x;
    if (i >= n) return;
    bf16 h, l; split_bf(in[i], h, l);
    oh[i] = h; ol[i] = l;
}

// pack wq|wk|wv -> [l][k][3D] hi/lo
__global__ void conv_qkv_w_k(const float* __restrict__ wq, const float* __restrict__ wk,
                             const float* __restrict__ wv) {
    int i = blockIdx.x * blockDim.x + threadIdx.x;
    if (i >= NL * DM * D3) return;
    int l = i / (DM * D3);
    int r = i - l * DM * D3;
    int k = r / D3, n = r - k * D3;
    int which = n / DM, nn = n - which * DM;
    const float* src = (which == 0) ? wq : (which == 1) ? wk : wv;
    float v = src[(long)l * DM * DM + (long)k * DM + nn];
    bf16 h, lo; split_bf(v, h, lo);
    w_qkvh[i] = h; w_qkvl[i] = lo;
}

__global__ void pack_qkv_b_k(const float* __restrict__ bq, const float* __restrict__ bk,
                             const float* __restrict__ bv) {
    int i = blockIdx.x * blockDim.x + threadIdx.x;
    if (i >= NL * D3) return;
    int l = i / D3, n = i - l * D3;
    int which = n / DM, nn = n - which * DM;
    const float* src = (which == 0) ? bq : (which == 1) ? bk : bv;
    g_bqkv[i] = src[l * DM + nn];
}

// transpose+split tok_emb [V,D] -> [D][VP] (zero-pad v >= VV)
__global__ void conv_te_t_k(const float* __restrict__ te) {
    __shared__ float t[32][33];
    int v0 = blockIdx.x * 32, d0 = blockIdx.y * 32;
    int tx = threadIdx.x, ty = threadIdx.y;   // 32 x 8
#pragma unroll
    for (int j = 0; j < 4; j++) {
        int v = v0 + ty + j * 8;
        t[ty + j * 8][tx] = (v < VV) ? te[(long)v * DM + d0 + tx] : 0.f;
    }
    __syncthreads();
#pragma unroll
    for (int j = 0; j < 4; j++) {
        int d = d0 + ty + j * 8;
        bf16 h, l; split_bf(t[tx][ty + j * 8], h, l);
        g_teh[(long)d * VP + v0 + tx] = h;
        g_tel[(long)d * VP + v0 + tx] = l;
    }
}

// ---------------- embed ----------------------------------------------------
__global__ void embed_k(const int* __restrict__ idx,
                        const float* __restrict__ tok,
                        const float* __restrict__ pos) {
    int i = blockIdx.x * blockDim.x + threadIdx.x;
    if (i >= MTOK * DM) return;
    int m = i / DM, d = i % DM;
    int s = m % SS;
    int w = idx[m];
    g_x[i] = tok[(long)w * DM + d] + pos[s * DM + d];
}

// ---------------- layernorm -> hi/lo bf16 ----------------------------------
__global__ void ln_bf_k(const float* __restrict__ in, bf16* __restrict__ oh,
                        bf16* __restrict__ ol, const float* __restrict__ w,
                        const float* __restrict__ b) {
    int row = blockIdx.x;
    const float* x = in + (long)row * DM;
    int tid = threadIdx.x;
    float s = 0.f, s2 = 0.f;
    for (int d = tid; d < DM; d += blockDim.x) {
        float v = x[d]; s += v; s2 += v * v;
    }
    __shared__ float rs[8], rs2[8], bc[2];
    for (int o = 16; o > 0; o >>= 1) {
        s  += __shfl_xor_sync(0xffffffffu, s,  o);
        s2 += __shfl_xor_sync(0xffffffffu, s2, o);
    }
    if ((tid & 31) == 0) { rs[tid >> 5] = s; rs2[tid >> 5] = s2; }
    __syncthreads();
    if (tid == 0) {
        float a = 0.f, a2 = 0.f;
        for (int i = 0; i < 8; i++) { a += rs[i]; a2 += rs2[i]; }
        float mean = a / DM;
        float var  = a2 / DM - mean * mean;
        bc[0] = mean; bc[1] = rsqrtf(var + 1e-5f);
    }
    __syncthreads();
    float mean = bc[0], inv = bc[1];
    for (int d = tid; d < DM; d += blockDim.x) {
        float v = (x[d] - mean) * inv * w[d] + b[d];
        bf16 h, l; split_bf(v, h, l);
        oh[(long)row * DM + d] = h;
        ol[(long)row * DM + d] = l;
    }
}

// ---------------- MMA helpers ----------------------------------------------
__device__ __forceinline__ void ldsm_x4(uint32_t* r, const void* p) {
    uint32_t a = (uint32_t)__cvta_generic_to_shared(p);
    asm volatile("ldmatrix.sync.aligned.m8n8.x4.shared.b16 {%0,%1,%2,%3}, [%4];"
                 : "=r"(r[0]), "=r"(r[1]), "=r"(r[2]), "=r"(r[3]) : "r"(a));
}
__device__ __forceinline__ void ldsm_x2_t(uint32_t* r, const void* p) {
    uint32_t a = (uint32_t)__cvta_generic_to_shared(p);
    asm volatile("ldmatrix.sync.aligned.m8n8.x2.trans.shared.b16 {%0,%1}, [%2];"
                 : "=r"(r[0]), "=r"(r[1]) : "r"(a));
}
__device__ __forceinline__ void mma_bf16(float* c, const uint32_t* a, const uint32_t* b) {
    asm volatile(
        "mma.sync.aligned.m16n8k16.row.col.f32.bf16.bf16.f32 "
        "{%0,%1,%2,%3}, {%4,%5,%6,%7}, {%8,%9}, {%0,%1,%2,%3};"
        : "+f"(c[0]), "+f"(c[1]), "+f"(c[2]), "+f"(c[3])
        : "r"(a[0]), "r"(a[1]), "r"(a[2]), "r"(a[3]), "r"(b[0]), "r"(b[1]));
}
__device__ __forceinline__ void cp16(void* dst, const void* src) {
    uint32_t d = (uint32_t)__cvta_generic_to_shared(dst);
    asm volatile("cp.async.cg.shared.global [%0], [%1], 16;" :: "r"(d), "l"(src));
}

// smem layout (bf16 units, per stage)
#define ASTR2 40
#define BSTR2 136
#define A_OFF 0
#define AL_OFF 5120          // 128*40
#define BH_OFF 10240
#define BL_OFF 14592         // + 32*136
#define SSZ   18944          // stage size in bf16
#define SMEM_BYTES (2*SSZ*2) // 75776

// ---------------- GEMM: C[M,N] = A @ B, A/B pre-split bf16 hi/lo ------------
// EPI: 0 = fp32 out (+bias opt), 1 = bf16 hi/lo gelu(acc+bias), 2 = fp32 bias+res
// NG : N-guard on epilogue stores (LM head)
template <int EPI, bool NG>
__global__ __launch_bounds__(256)
void gemm_bf(const bf16* __restrict__ Ah_g, const bf16* __restrict__ Al_g,
             const bf16* __restrict__ Bh_g, const bf16* __restrict__ Bl_g,
             const float* __restrict__ bias, const float* __restrict__ res,
             float* __restrict__ C, bf16* __restrict__ Ch, bf16* __restrict__ Cl,
             int Ndim, int Kdim, int ldb, int ldc) {
    extern __shared__ bf16 sm[];

    const int tid  = threadIdx.x;
    const int lane = tid & 31;
    const int wid  = tid >> 5;
    const int wm   = (wid >> 2) * 64;
    const int wn   = (wid & 3) * 32;
    const int a0   = blockIdx.y * 128;
    const int b0   = blockIdx.x * 128;
    const int niter = Kdim >> 5;

    float acc[4][4][4];
#pragma unroll
    for (int i = 0; i < 4; i++)
#pragma unroll
        for (int j = 0; j < 4; j++)
#pragma unroll
            for (int e = 0; e < 4; e++) acc[i][j][e] = 0.f;

    // stage loader
    auto load_stage = [&](int buf, int k0) {
        bf16* s = sm + buf * SSZ;
#pragma unroll
        for (int i = 0; i < 2; i++) {
            int g = tid + i * 256;           // A: 512 granules (128r x 4)
            int r = g >> 2, c = (g & 3) * 8;
            const bf16* srcH = Ah_g + (size_t)(a0 + r) * Kdim + k0 + c;
            const bf16* srcL = Al_g + (size_t)(a0 + r) * Kdim + k0 + c;
            cp16(&s[A_OFF  + r * ASTR2 + c], srcH);
            cp16(&s[AL_OFF + r * ASTR2 + c], srcL);
        }
#pragma unroll
        for (int i = 0; i < 2; i++) {
            int g = tid + i * 256;           // B: 512 granules (32r x 16)
            int r = g >> 4, c = (g & 15) * 8;
            const bf16* srcH = Bh_g + (size_t)(k0 + r) * ldb + b0 + c;
            const bf16* srcL = Bl_g + (size_t)(k0 + r) * ldb + b0 + c;
            cp16(&s[BH_OFF + r * BSTR2 + c], srcH);
            cp16(&s[BL_OFF + r * BSTR2 + c], srcL);
        }
        asm volatile("cp.async.commit_group;");
    };

    load_stage(0, 0);

    for (int it = 0; it < niter; it++) {
        if (it + 1 < niter) {
            load_stage((it + 1) & 1, (it + 1) << 5);
            asm volatile("cp.async.wait_group 1;");
        } else {
            asm volatile("cp.async.wait_group 0;");
        }
        __syncthreads();

        bf16* s   = sm + (it & 1) * SSZ;
        bf16* sAh = s + A_OFF;
        bf16* sAl = s + AL_OFF;
        bf16* sBh = s + BH_OFF;
        bf16* sBl = s + BL_OFF;

#pragma unroll
        for (int ks = 0; ks < 2; ks++) {
            uint32_t ah[4][4], al[4][4], bh[4][2], bl[4][2];
            int arow = wm + (lane & 15);
            int acol = ks * 16 + (lane >> 4) * 8;
#pragma unroll
            for (int mt = 0; mt < 4; mt++) {
                ldsm_x4(ah[mt], &sAh[(arow + mt * 16) * ASTR2 + acol]);
                ldsm_x4(al[mt], &sAl[(arow + mt * 16) * ASTR2 + acol]);
            }
            int brow = ks * 16 + (lane & 15);
#pragma unroll
            for (int nt = 0; nt < 4; nt++) {
                ldsm_x2_t(bh[nt], &sBh[brow * BSTR2 + wn + nt * 8]);
                ldsm_x2_t(bl[nt], &sBl[brow * BSTR2 + wn + nt * 8]);
            }
#pragma unroll
            for (int mt = 0; mt < 4; mt++)
#pragma unroll
                for (int nt = 0; nt < 4; nt++) {
                    mma_bf16(acc[mt][nt], ah[mt], bh[nt]);
                    mma_bf16(acc[mt][nt], al[mt], bh[nt]);
                    mma_bf16(acc[mt][nt], ah[mt], bl[nt]);
                }
        }
        __syncthreads();
    }

    // ---- epilogue ----
#pragma unroll
    for (int mt = 0; mt < 4; mt++) {
        long r0 = a0 + wm + mt * 16 + (lane >> 2);
        long r1 = r0 + 8;
#pragma unroll
        for (int nt = 0; nt < 4; nt++) {
            int cb = b0 + wn + nt * 8 + (lane & 3) * 2;
#pragma unroll
            for (int j = 0; j < 2; j++) {
                int col = cb + j;
                if (NG && col >= Ndim) continue;
                float v0 = acc[mt][nt][j];
                float v1 = acc[mt][nt][2 + j];
                if (bias) { float bb = bias[col]; v0 += bb; v1 += bb; }
                if (EPI == 1) {
                    v0 = gelu_f(v0); v1 = gelu_f(v1);
                    bf16 h0, l0, h1, l1;
                    split_bf(v0, h0, l0); split_bf(v1, h1, l1);
                    Ch[r0 * ldc + col] = h0; Cl[r0 * ldc + col] = l0;
                    Ch[r1 * ldc + col] = h1; Cl[r1 * ldc + col] = l1;
                } else {
                    if (EPI == 2) {
                        v0 += res[r0 * ldc + col];
                        v1 += res[r1 * ldc + col];
                    }
                    C[r0 * ldc + col] = v0;
                    C[r1 * ldc + col] = v1;
                }
            }
        }
    }
}

// ---------------- causal attention: one block per (q, h, b) ----------------
// reads g_qkv [M, 2304] (q|k|v), writes hi/lo bf16 into g_ah/g_al
__global__ __launch_bounds__(128)
void attn_k() {
    int q = blockIdx.x, h = blockIdx.y, b = blockIdx.z;
    int tid = threadIdx.x;
    int m0 = b * SS;

    __shared__ float qs[HDIM];
    __shared__ float sc[SS];
    __shared__ float rbuf[5];
    __shared__ float part[128];

    const float* qp = g_qkv + (long)(m0 + q) * D3 + h * HDIM;
    if (tid < HDIM) qs[tid] = qp[tid];
    __syncthreads();

    int nk = q + 1;
    float lmax = -1e30f;
    for (int j = tid; j < nk; j += 128) {
        const float4* kp = (const float4*)(g_qkv + (long)(m0 + j) * D3 + DM + h * HDIM);
        float s = 0.f;
#pragma unroll
        for (int d4 = 0; d4 < HDIM / 4; d4++) {
            float4 kv = kp[d4];
            s += qs[d4 * 4 + 0] * kv.x + qs[d4 * 4 + 1] * kv.y
               + qs[d4 * 4 + 2] * kv.z + qs[d4 * 4 + 3] * kv.w;
        }
        s *= 0.125f;
        sc[j] = s;
        lmax = fmaxf(lmax, s);
    }
    for (int o = 16; o > 0; o >>= 1) lmax = fmaxf(lmax, __shfl_xor_sync(0xffffffffu, lmax, o));
    if ((tid & 31) == 0) rbuf[tid >> 5] = lmax;
    __syncthreads();
    if (tid == 0) {
        float m = fmaxf(fmaxf(rbuf[0], rbuf[1]), fmaxf(rbuf[2], rbuf[3]));
        rbuf[4] = m;
    }
    __syncthreads();
    float smax = rbuf[4];
    __syncthreads();

    float lsum = 0.f;
    for (int j = tid; j < nk; j += 128) {
        float e = __expf(sc[j] - smax);
        sc[j] = e;
        lsum += e;
    }
    for (int o = 16; o > 0; o >>= 1) lsum += __shfl_xor_sync(0xffffffffu, lsum, o);
    if ((tid & 31) == 0) rbuf[tid >> 5] = lsum;
    __syncthreads();
    if (tid == 0) rbuf[4] = 1.0f / (rbuf[0] + rbuf[1] + rbuf[2] + rbuf[3]);
    __syncthreads();
    float inv = rbuf[4];

    int d = tid & 63;
    int hv = tid >> 6;
    float acc = 0.f;
    for (int j = hv; j < nk; j += 2)
        acc += sc[j] * g_qkv[(long)(m0 + j) * D3 + 2 * DM + h * HDIM + d];
    part[tid] = acc;
    __syncthreads();
    if (tid < 64) {
        float o = (part[tid] + part[tid + 64]) * inv;
        bf16 hh, ll; split_bf(o, hh, ll);
        long idx = (long)(m0 + q) * DM + h * HDIM + tid;
        g_ah[idx] = hh; g_al[idx] = ll;
    }
}

// ---------------- host orchestration ---------------------------------------
extern "C" void kernel_launch(void* const* d_in, const int* in_sizes, int n_in,
                              void* d_out, int out_size) {
    const int*   word_idx = (const int*)  d_in[0];
    const float* tok_emb  = (const float*)d_in[1];
    const float* pos_emb  = (const float*)d_in[2];
    const float* ln1_w    = (const float*)d_in[3];
    const float* ln1_b    = (const float*)d_in[4];
    const float* wq       = (const float*)d_in[5];
    const float* bq       = (const float*)d_in[6];
    const float* wk       = (const float*)d_in[7];
    const float* bk       = (const float*)d_in[8];
    const float* wv       = (const float*)d_in[9];
    const float* bv       = (const float*)d_in[10];
    const float* wo       = (const float*)d_in[11];
    const float* bo       = (const float*)d_in[12];
    const float* ln2_w    = (const float*)d_in[13];
    const float* ln2_b    = (const float*)d_in[14];
    const float* w1       = (const float*)d_in[15];
    const float* b1       = (const float*)d_in[16];
    const float* w2       = (const float*)d_in[17];
    const float* b2       = (const float*)d_in[18];
    const float* lnf_w    = (const float*)d_in[19];
    const float* lnf_b    = (const float*)d_in[20];
    float* out = (float*)d_out;

    float *gx, *gqkv, *gbq;
    bf16 *ghh, *ghl, *gah, *gal, *gfh, *gfl;
    bf16 *wqkvh, *wqkvl, *woh, *wol, *w1h, *w1l, *w2h, *w2l, *teh, *tel;
    cudaGetSymbolAddress((void**)&gx,    g_x);
    cudaGetSymbolAddress((void**)&gqkv,  g_qkv);
    cudaGetSymbolAddress((void**)&gbq,   g_bqkv);
    cudaGetSymbolAddress((void**)&ghh,   g_hh);
    cudaGetSymbolAddress((void**)&ghl,   g_hl);
    cudaGetSymbolAddress((void**)&gah,   g_ah);
    cudaGetSymbolAddress((void**)&gal,   g_al);
    cudaGetSymbolAddress((void**)&gfh,   g_fh);
    cudaGetSymbolAddress((void**)&gfl,   g_fl);
    cudaGetSymbolAddress((void**)&wqkvh, w_qkvh);
    cudaGetSymbolAddress((void**)&wqkvl, w_qkvl);
    cudaGetSymbolAddress((void**)&woh,   w_oh);
    cudaGetSymbolAddress((void**)&wol,   w_ol);
    cudaGetSymbolAddress((void**)&w1h,   w_1h);
    cudaGetSymbolAddress((void**)&w1l,   w_1l);
    cudaGetSymbolAddress((void**)&w2h,   w_2h);
    cudaGetSymbolAddress((void**)&w2l,   w_2l);
    cudaGetSymbolAddress((void**)&teh,   g_teh);
    cudaGetSymbolAddress((void**)&tel,   g_tel);

    // raise dynamic smem limit on each instantiation (idempotent, host-side)
    cudaFuncSetAttribute(gemm_bf<0,false>, cudaFuncAttributeMaxDynamicSharedMemorySize, SMEM_BYTES);
    cudaFuncSetAttribute(gemm_bf<1,false>, cudaFuncAttributeMaxDynamicSharedMemorySize, SMEM_BYTES);
    cudaFuncSetAttribute(gemm_bf<2,false>, cudaFuncAttributeMaxDynamicSharedMemorySize, SMEM_BYTES);
    cudaFuncSetAttribute(gemm_bf<0,true>,  cudaFuncAttributeMaxDynamicSharedMemorySize, SMEM_BYTES);

    // ---- one-time conversions ----
    conv_qkv_w_k<<<(NL * DM * D3 + 255) / 256, 256>>>(wq, wk, wv);
    pack_qkv_b_k<<<(NL * D3 + 255) / 256, 256>>>(bq, bk, bv);
    conv_split_k<<<(NL * DM * DM + 255) / 256, 256>>>(wo, woh, wol, NL * DM * DM);
    conv_split_k<<<(NL * DM * FF + 255) / 256, 256>>>(w1, w1h, w1l, NL * DM * FF);
    conv_split_k<<<(NL * FF * DM + 255) / 256, 256>>>(w2, w2h, w2l, NL * FF * DM);
    conv_te_t_k<<<dim3(VP / 32, DM / 32), dim3(32, 8)>>>(tok_emb);

    embed_k<<<(MTOK * DM + 255) / 256, 256>>>(word_idx, tok_emb, pos_emb);

    dim3 grdQKV(D3 / 128, MTOK / 128);   // 18 x 16
    dim3 grdD  (DM / 128, MTOK / 128);   // 6 x 16
    dim3 grdF  (FF / 128, MTOK / 128);   // 24 x 16
    dim3 grdV  (VP / 128, MTOK / 128);   // 393 x 16

    for (int l = 0; l < NL; l++) {
        ln_bf_k<<<MTOK, 256>>>(gx, ghh, ghl, ln1_w + l * DM, ln1_b + l * DM);
        gemm_bf<0,false><<<grdQKV, 256, SMEM_BYTES>>>(
            ghh, ghl, wqkvh + (size_t)l * DM * D3, wqkvl + (size_t)l * DM * D3,
            gbq + l * D3, nullptr, gqkv, nullptr, nullptr, D3, DM, D3, D3);
        attn_k<<<dim3(SS, NH, BBAT), 128>>>();
        gemm_bf<2,false><<<grdD, 256, SMEM_BYTES>>>(
            gah, gal, woh + (size_t)l * DM * DM, wol + (size_t)l * DM * DM,
            bo + l * DM, gx, gx, nullptr, nullptr, DM, DM, DM, DM);
        ln_bf_k<<<MTOK, 256>>>(gx, ghh, ghl, ln2_w + l * DM, ln2_b + l * DM);
        gemm_bf<1,false><<<grdF, 256, SMEM_BYTES>>>(
            ghh, ghl, w1h + (size_t)l * DM * FF, w1l + (size_t)l * DM * FF,
            b1 + l * FF, nullptr, nullptr, gfh, gfl, FF, DM, FF, FF);
        gemm_bf<2,false><<<grdD, 256, SMEM_BYTES>>>(
            gfh, gfl, w2h + (size_t)l * FF * DM, w2l + (size_t)l * FF * DM,
            b2 + l * DM, gx, gx, nullptr, nullptr, DM, FF, DM, DM);
    }

    ln_bf_k<<<MTOK, 256>>>(gx, ghh, ghl, lnf_w, lnf_b);
    // LM head: logits = h @ te_t  (te_t [D][VP] pre-transposed, zero-padded)
    gemm_bf<0,true><<<grdV, 256, SMEM_BYTES>>>(
        ghh, ghl, teh, tel, nullptr, nullptr, out, nullptr, nullptr,
        VV, DM, VP, VV);
}

// round 7
// speedup vs baseline: 2.1895x; 1.0811x over previous
#include <cuda_runtime.h>
#include <cuda_bf16.h>
#include <cstdint>
#include <math.h>

#define VV   50257
#define VP   50304            // V padded to multiple of 128
#define SS   1024
#define BBAT 2
#define DM   768
#define NH   12
#define HDIM 64
#define FF   3072
#define NL   2
#define MTOK (BBAT*SS)        // 2048
#define D3   (3*DM)           // 2304

typedef __nv_bfloat16 bf16;

// ---------------- persistent scratch (device globals) ----------------------
__device__ float g_x   [MTOK*DM];
__device__ float g_qkv [MTOK*D3];
__device__ bf16  g_hh  [MTOK*DM],  g_hl[MTOK*DM];
__device__ bf16  g_ah  [MTOK*DM],  g_al[MTOK*DM];
__device__ bf16  g_fh  [MTOK*FF],  g_fl[MTOK*FF];
__device__ bf16  w_qkvh[NL*DM*D3], w_qkvl[NL*DM*D3];   // [l][k][n3]
__device__ bf16  w_oh  [NL*DM*DM], w_ol [NL*DM*DM];
__device__ bf16  w_1h  [NL*DM*FF], w_1l [NL*DM*FF];
__device__ bf16  w_2h  [NL*FF*DM], w_2l [NL*FF*DM];
__device__ bf16  g_teh [DM*VP],    g_tel[DM*VP];       // [d][v] transposed, padded
__device__ float g_bqkv[NL*D3];

__device__ __forceinline__ void split_bf(float v, bf16& h, bf16& l) {
    h = __float2bfloat16_rn(v);
    l = __float2bfloat16_rn(v - __bfloat162float(h));
}
__device__ __forceinline__ float gelu_f(float z) {
    float z3 = z * z * z;
    return 0.5f * z * (1.0f + tanhf(0.7978845608028654f * (z + 0.044715f * z3)));
}

// ---------------- conversion kernels ---------------------------------------
__global__ void conv_split_k(const float* __restrict__ in, bf16* __restrict__ oh,
                             bf16* __restrict__ ol, int n) {
    int i = blockIdx.x * blockDim.x + threadIdx.x;
    if (i >= n) return;
    bf16 h, l; split_bf(in[i], h, l);
    oh[i] = h; ol[i] = l;
}

// pack wq|wk|wv -> [l][k][3D] hi/lo
__global__ void conv_qkv_w_k(const float* __restrict__ wq, const float* __restrict__ wk,
                             const float* __restrict__ wv) {
    int i = blockIdx.x * blockDim.x + threadIdx.x;
    if (i >= NL * DM * D3) return;
    int l = i / (DM * D3);
    int r = i - l * DM * D3;
    int k = r / D3, n = r - k * D3;
    int which = n / DM, nn = n - which * DM;
    const float* src = (which == 0) ? wq : (which == 1) ? wk : wv;
    float v = src[(long)l * DM * DM + (long)k * DM + nn];
    bf16 h, lo; split_bf(v, h, lo);
    w_qkvh[i] = h; w_qkvl[i] = lo;
}

__global__ void pack_qkv_b_k(const float* __restrict__ bq, const float* __restrict__ bk,
                             const float* __restrict__ bv) {
    int i = blockIdx.x * blockDim.x + threadIdx.x;
    if (i >= NL * D3) return;
    int l = i / D3, n = i - l * D3;
    int which = n / DM, nn = n - which * DM;
    const float* src = (which == 0) ? bq : (which == 1) ? bk : bv;
    g_bqkv[i] = src[l * DM + nn];
}

// transpose+split tok_emb [V,D] -> [D][VP] (zero-pad v >= VV)
__global__ void conv_te_t_k(const float* __restrict__ te) {
    __shared__ float t[32][33];
    int v0 = blockIdx.x * 32, d0 = blockIdx.y * 32;
    int tx = threadIdx.x, ty = threadIdx.y;   // 32 x 8
#pragma unroll
    for (int j = 0; j < 4; j++) {
        int v = v0 + ty + j * 8;
        t[ty + j * 8][tx] = (v < VV) ? te[(long)v * DM + d0 + tx] : 0.f;
    }
    __syncthreads();
#pragma unroll
    for (int j = 0; j < 4; j++) {
        int d = d0 + ty + j * 8;
        bf16 h, l; split_bf(t[tx][ty + j * 8], h, l);
        g_teh[(long)d * VP + v0 + tx] = h;
        g_tel[(long)d * VP + v0 + tx] = l;
    }
}

// ---------------- embed ----------------------------------------------------
__global__ void embed_k(const int* __restrict__ idx,
                        const float* __restrict__ tok,
                        const float* __restrict__ pos) {
    int i = blockIdx.x * blockDim.x + threadIdx.x;
    if (i >= MTOK * DM) return;
    int m = i / DM, d = i % DM;
    int s = m % SS;
    int w = idx[m];
    g_x[i] = tok[(long)w * DM + d] + pos[s * DM + d];
}

// ---------------- layernorm -> hi/lo bf16 ----------------------------------
__global__ void ln_bf_k(const float* __restrict__ in, bf16* __restrict__ oh,
                        bf16* __restrict__ ol, const float* __restrict__ w,
                        const float* __restrict__ b) {
    int row = blockIdx.x;
    const float* x = in + (long)row * DM;
    int tid = threadIdx.x;
    float s = 0.f, s2 = 0.f;
    for (int d = tid; d < DM; d += blockDim.x) {
        float v = x[d]; s += v; s2 += v * v;
    }
    __shared__ float rs[8], rs2[8], bc[2];
    for (int o = 16; o > 0; o >>= 1) {
        s  += __shfl_xor_sync(0xffffffffu, s,  o);
        s2 += __shfl_xor_sync(0xffffffffu, s2, o);
    }
    if ((tid & 31) == 0) { rs[tid >> 5] = s; rs2[tid >> 5] = s2; }
    __syncthreads();
    if (tid == 0) {
        float a = 0.f, a2 = 0.f;
        for (int i = 0; i < 8; i++) { a += rs[i]; a2 += rs2[i]; }
        float mean = a / DM;
        float var  = a2 / DM - mean * mean;
        bc[0] = mean; bc[1] = rsqrtf(var + 1e-5f);
    }
    __syncthreads();
    float mean = bc[0], inv = bc[1];
    for (int d = tid; d < DM; d += blockDim.x) {
        float v = (x[d] - mean) * inv * w[d] + b[d];
        bf16 h, l; split_bf(v, h, l);
        oh[(long)row * DM + d] = h;
        ol[(long)row * DM + d] = l;
    }
}

// ---------------- MMA helpers ----------------------------------------------
__device__ __forceinline__ void ldsm_x4(uint32_t* r, const void* p) {
    uint32_t a = (uint32_t)__cvta_generic_to_shared(p);
    asm volatile("ldmatrix.sync.aligned.m8n8.x4.shared.b16 {%0,%1,%2,%3}, [%4];"
                 : "=r"(r[0]), "=r"(r[1]), "=r"(r[2]), "=r"(r[3]) : "r"(a));
}
__device__ __forceinline__ void ldsm_x2_t(uint32_t* r, const void* p) {
    uint32_t a = (uint32_t)__cvta_generic_to_shared(p);
    asm volatile("ldmatrix.sync.aligned.m8n8.x2.trans.shared.b16 {%0,%1}, [%2];"
                 : "=r"(r[0]), "=r"(r[1]) : "r"(a));
}
__device__ __forceinline__ void mma_bf16(float* c, const uint32_t* a, const uint32_t* b) {
    asm volatile(
        "mma.sync.aligned.m16n8k16.row.col.f32.bf16.bf16.f32 "
        "{%0,%1,%2,%3}, {%4,%5,%6,%7}, {%8,%9}, {%0,%1,%2,%3};"
        : "+f"(c[0]), "+f"(c[1]), "+f"(c[2]), "+f"(c[3])
        : "r"(a[0]), "r"(a[1]), "r"(a[2]), "r"(a[3]), "r"(b[0]), "r"(b[1]));
}
__device__ __forceinline__ void cp16(void* dst, const void* src) {
    uint32_t d = (uint32_t)__cvta_generic_to_shared(dst);
    asm volatile("cp.async.cg.shared.global [%0], [%1], 16;" :: "r"(d), "l"(src));
}

// smem layout (bf16 units, per stage)
#define ASTR2 40
#define BSTR2 136
#define A_OFF 0
#define AL_OFF 5120          // 128*40
#define BH_OFF 10240
#define BL_OFF 14592         // + 32*136
#define SSZ   18944          // stage size in bf16
#define NSTAGE 3
#define SMEM_BYTES (NSTAGE*SSZ*2)   // 113664

// ---------------- GEMM: C[M,N] = A @ B, A/B pre-split bf16 hi/lo ------------
// EPI: 0 = fp32 out (+bias opt), 1 = bf16 hi/lo gelu(acc+bias), 2 = fp32 bias+res
// NG : N-guard on epilogue stores (LM head)
template <int EPI, bool NG>
__global__ __launch_bounds__(256, 2)
void gemm_bf(const bf16* __restrict__ Ah_g, const bf16* __restrict__ Al_g,
             const bf16* __restrict__ Bh_g, const bf16* __restrict__ Bl_g,
             const float* __restrict__ bias, const float* __restrict__ res,
             float* __restrict__ C, bf16* __restrict__ Ch, bf16* __restrict__ Cl,
             int Ndim, int Kdim, int ldb, int ldc) {
    extern __shared__ bf16 sm[];

    const int tid  = threadIdx.x;
    const int lane = tid & 31;
    const int wid  = tid >> 5;
    const int wm   = (wid >> 2) * 64;
    const int wn   = (wid & 3) * 32;
    const int a0   = blockIdx.y * 128;
    const int b0   = blockIdx.x * 128;
    const int niter = Kdim >> 5;

    float acc[4][4][4];
#pragma unroll
    for (int i = 0; i < 4; i++)
#pragma unroll
        for (int j = 0; j < 4; j++)
#pragma unroll
            for (int e = 0; e < 4; e++) acc[i][j][e] = 0.f;

    auto load_stage = [&](int buf, int k0) {
        bf16* s = sm + buf * SSZ;
#pragma unroll
        for (int i = 0; i < 2; i++) {
            int g = tid + i * 256;           // A: 512 granules (128r x 4)
            int r = g >> 2, c = (g & 3) * 8;
            cp16(&s[A_OFF  + r * ASTR2 + c], Ah_g + (size_t)(a0 + r) * Kdim + k0 + c);
            cp16(&s[AL_OFF + r * ASTR2 + c], Al_g + (size_t)(a0 + r) * Kdim + k0 + c);
        }
#pragma unroll
        for (int i = 0; i < 2; i++) {
            int g = tid + i * 256;           // B: 512 granules (32r x 16)
            int r = g >> 4, c = (g & 15) * 8;
            cp16(&s[BH_OFF + r * BSTR2 + c], Bh_g + (size_t)(k0 + r) * ldb + b0 + c);
            cp16(&s[BL_OFF + r * BSTR2 + c], Bl_g + (size_t)(k0 + r) * ldb + b0 + c);
        }
        asm volatile("cp.async.commit_group;");
    };

    load_stage(0, 0);
    load_stage(1, 32);

    for (int it = 0; it < niter; it++) {
        if (it + 1 < niter) asm volatile("cp.async.wait_group 1;");
        else                asm volatile("cp.async.wait_group 0;");
        __syncthreads();

        // prefetch stage it+2 into ring slot (safe: distance-2 in 3-slot ring,
        // one barrier per iter bounds warp skew to a single iteration)
        if (it + 2 < niter) load_stage((it + 2) % NSTAGE, (it + 2) << 5);

        bf16* s   = sm + (it % NSTAGE) * SSZ;
        bf16* sAh = s + A_OFF;
        bf16* sAl = s + AL_OFF;
        bf16* sBh = s + BH_OFF;
        bf16* sBl = s + BL_OFF;

#pragma unroll
        for (int ks = 0; ks < 2; ks++) {
            uint32_t ah[4][4], al[4][4], bh[4][2], bl[4][2];
            int arow = wm + (lane & 15);
            int acol = ks * 16 + (lane >> 4) * 8;
#pragma unroll
            for (int mt = 0; mt < 4; mt++) {
                ldsm_x4(ah[mt], &sAh[(arow + mt * 16) * ASTR2 + acol]);
                ldsm_x4(al[mt], &sAl[(arow + mt * 16) * ASTR2 + acol]);
            }
            int brow = ks * 16 + (lane & 15);
#pragma unroll
            for (int nt = 0; nt < 4; nt++) {
                ldsm_x2_t(bh[nt], &sBh[brow * BSTR2 + wn + nt * 8]);
                ldsm_x2_t(bl[nt], &sBl[brow * BSTR2 + wn + nt * 8]);
            }
#pragma unroll
            for (int mt = 0; mt < 4; mt++)
#pragma unroll
                for (int nt = 0; nt < 4; nt++) {
                    mma_bf16(acc[mt][nt], ah[mt], bh[nt]);
                    mma_bf16(acc[mt][nt], al[mt], bh[nt]);
                    mma_bf16(acc[mt][nt], ah[mt], bl[nt]);
                }
        }
    }

    // ---- epilogue ----
#pragma unroll
    for (int mt = 0; mt < 4; mt++) {
        long r0 = a0 + wm + mt * 16 + (lane >> 2);
        long r1 = r0 + 8;
#pragma unroll
        for (int nt = 0; nt < 4; nt++) {
            int cb = b0 + wn + nt * 8 + (lane & 3) * 2;
#pragma unroll
            for (int j = 0; j < 2; j++) {
                int col = cb + j;
                if (NG && col >= Ndim) continue;
                float v0 = acc[mt][nt][j];
                float v1 = acc[mt][nt][2 + j];
                if (bias) { float bb = bias[col]; v0 += bb; v1 += bb; }
                if (EPI == 1) {
                    v0 = gelu_f(v0); v1 = gelu_f(v1);
                    bf16 h0, l0, h1, l1;
                    split_bf(v0, h0, l0); split_bf(v1, h1, l1);
                    Ch[r0 * ldc + col] = h0; Cl[r0 * ldc + col] = l0;
                    Ch[r1 * ldc + col] = h1; Cl[r1 * ldc + col] = l1;
                } else {
                    if (EPI == 2) {
                        v0 += res[r0 * ldc + col];
                        v1 += res[r1 * ldc + col];
                    }
                    C[r0 * ldc + col] = v0;
                    C[r1 * ldc + col] = v1;
                }
            }
        }
    }
}

// ---------------- causal attention: one block per (q, h, b) ----------------
__global__ __launch_bounds__(128)
void attn_k() {
    int q = blockIdx.x, h = blockIdx.y, b = blockIdx.z;
    int tid = threadIdx.x;
    int m0 = b * SS;

    __shared__ float qs[HDIM];
    __shared__ float sc[SS];
    __shared__ float rbuf[5];
    __shared__ float part[128];

    const float* qp = g_qkv + (long)(m0 + q) * D3 + h * HDIM;
    if (tid < HDIM) qs[tid] = qp[tid];
    __syncthreads();

    int nk = q + 1;
    float lmax = -1e30f;
    for (int j = tid; j < nk; j += 128) {
        const float4* kp = (const float4*)(g_qkv + (long)(m0 + j) * D3 + DM + h * HDIM);
        float s = 0.f;
#pragma unroll
        for (int d4 = 0; d4 < HDIM / 4; d4++) {
            float4 kv = kp[d4];
            s += qs[d4 * 4 + 0] * kv.x + qs[d4 * 4 + 1] * kv.y
               + qs[d4 * 4 + 2] * kv.z + qs[d4 * 4 + 3] * kv.w;
        }
        s *= 0.125f;
        sc[j] = s;
        lmax = fmaxf(lmax, s);
    }
    for (int o = 16; o > 0; o >>= 1) lmax = fmaxf(lmax, __shfl_xor_sync(0xffffffffu, lmax, o));
    if ((tid & 31) == 0) rbuf[tid >> 5] = lmax;
    __syncthreads();
    if (tid == 0) {
        float m = fmaxf(fmaxf(rbuf[0], rbuf[1]), fmaxf(rbuf[2], rbuf[3]));
        rbuf[4] = m;
    }
    __syncthreads();
    float smax = rbuf[4];
    __syncthreads();

    float lsum = 0.f;
    for (int j = tid; j < nk; j += 128) {
        float e = __expf(sc[j] - smax);
        sc[j] = e;
        lsum += e;
    }
    for (int o = 16; o > 0; o >>= 1) lsum += __shfl_xor_sync(0xffffffffu, lsum, o);
    if ((tid & 31) == 0) rbuf[tid >> 5] = lsum;
    __syncthreads();
    if (tid == 0) rbuf[4] = 1.0f / (rbuf[0] + rbuf[1] + rbuf[2] + rbuf[3]);
    __syncthreads();
    float inv = rbuf[4];

    int d = tid & 63;
    int hv = tid >> 6;
    float acc = 0.f;
    for (int j = hv; j < nk; j += 2)
        acc += sc[j] * g_qkv[(long)(m0 + j) * D3 + 2 * DM + h * HDIM + d];
    part[tid] = acc;
    __syncthreads();
    if (tid < 64) {
        float o = (part[tid] + part[tid + 64]) * inv;
        bf16 hh, ll; split_bf(o, hh, ll);
        long idx = (long)(m0 + q) * DM + h * HDIM + tid;
        g_ah[idx] = hh; g_al[idx] = ll;
    }
}

// ---------------- host orchestration ---------------------------------------
extern "C" void kernel_launch(void* const* d_in, const int* in_sizes, int n_in,
                              void* d_out, int out_size) {
    const int*   word_idx = (const int*)  d_in[0];
    const float* tok_emb  = (const float*)d_in[1];
    const float* pos_emb  = (const float*)d_in[2];
    const float* ln1_w    = (const float*)d_in[3];
    const float* ln1_b    = (const float*)d_in[4];
    const float* wq       = (const float*)d_in[5];
    const float* bq       = (const float*)d_in[6];
    const float* wk       = (const float*)d_in[7];
    const float* bk       = (const float*)d_in[8];
    const float* wv       = (const float*)d_in[9];
    const float* bv       = (const float*)d_in[10];
    const float* wo       = (const float*)d_in[11];
    const float* bo       = (const float*)d_in[12];
    const float* ln2_w    = (const float*)d_in[13];
    const float* ln2_b    = (const float*)d_in[14];
    const float* w1       = (const float*)d_in[15];
    const float* b1       = (const float*)d_in[16];
    const float* w2       = (const float*)d_in[17];
    const float* b2       = (const float*)d_in[18];
    const float* lnf_w    = (const float*)d_in[19];
    const float* lnf_b    = (const float*)d_in[20];
    float* out = (float*)d_out;

    float *gx, *gqkv, *gbq;
    bf16 *ghh, *ghl, *gah, *gal, *gfh, *gfl;
    bf16 *wqkvh, *wqkvl, *woh, *wol, *w1h, *w1l, *w2h, *w2l, *teh, *tel;
    cudaGetSymbolAddress((void**)&gx,    g_x);
    cudaGetSymbolAddress((void**)&gqkv,  g_qkv);
    cudaGetSymbolAddress((void**)&gbq,   g_bqkv);
    cudaGetSymbolAddress((void**)&ghh,   g_hh);
    cudaGetSymbolAddress((void**)&ghl,   g_hl);
    cudaGetSymbolAddress((void**)&gah,   g_ah);
    cudaGetSymbolAddress((void**)&gal,   g_al);
    cudaGetSymbolAddress((void**)&gfh,   g_fh);
    cudaGetSymbolAddress((void**)&gfl,   g_fl);
    cudaGetSymbolAddress((void**)&wqkvh, w_qkvh);
    cudaGetSymbolAddress((void**)&wqkvl, w_qkvl);
    cudaGetSymbolAddress((void**)&woh,   w_oh);
    cudaGetSymbolAddress((void**)&wol,   w_ol);
    cudaGetSymbolAddress((void**)&w1h,   w_1h);
    cudaGetSymbolAddress((void**)&w1l,   w_1l);
    cudaGetSymbolAddress((void**)&w2h,   w_2h);
    cudaGetSymbolAddress((void**)&w2l,   w_2l);
    cudaGetSymbolAddress((void**)&teh,   g_teh);
    cudaGetSymbolAddress((void**)&tel,   g_tel);

    cudaFuncSetAttribute(gemm_bf<0,false>, cudaFuncAttributeMaxDynamicSharedMemorySize, SMEM_BYTES);
    cudaFuncSetAttribute(gemm_bf<1,false>, cudaFuncAttributeMaxDynamicSharedMemorySize, SMEM_BYTES);
    cudaFuncSetAttribute(gemm_bf<2,false>, cudaFuncAttributeMaxDynamicSharedMemorySize, SMEM_BYTES);
    cudaFuncSetAttribute(gemm_bf<0,true>,  cudaFuncAttributeMaxDynamicSharedMemorySize, SMEM_BYTES);

    // ---- one-time conversions ----
    conv_qkv_w_k<<<(NL * DM * D3 + 255) / 256, 256>>>(wq, wk, wv);
    pack_qkv_b_k<<<(NL * D3 + 255) / 256, 256>>>(bq, bk, bv);
    conv_split_k<<<(NL * DM * DM + 255) / 256, 256>>>(wo, woh, wol, NL * DM * DM);
    conv_split_k<<<(NL * DM * FF + 255) / 256, 256>>>(w1, w1h, w1l, NL * DM * FF);
    conv_split_k<<<(NL * FF * DM + 255) / 256, 256>>>(w2, w2h, w2l, NL * FF * DM);
    conv_te_t_k<<<dim3(VP / 32, DM / 32), dim3(32, 8)>>>(tok_emb);

    embed_k<<<(MTOK * DM + 255) / 256, 256>>>(word_idx, tok_emb, pos_emb);

    dim3 grdQKV(D3 / 128, MTOK / 128);   // 18 x 16
    dim3 grdD  (DM / 128, MTOK / 128);   // 6 x 16
    dim3 grdF  (FF / 128, MTOK / 128);   // 24 x 16
    dim3 grdV  (VP / 128, MTOK / 128);   // 393 x 16

    for (int l = 0; l < NL; l++) {
        ln_bf_k<<<MTOK, 256>>>(gx, ghh, ghl, ln1_w + l * DM, ln1_b + l * DM);
        gemm_bf<0,false><<<grdQKV, 256, SMEM_BYTES>>>(
            ghh, ghl, wqkvh + (size_t)l * DM * D3, wqkvl + (size_t)l * DM * D3,
            gbq + l * D3, nullptr, gqkv, nullptr, nullptr, D3, DM, D3, D3);
        attn_k<<<dim3(SS, NH, BBAT), 128>>>();
        gemm_bf<2,false><<<grdD, 256, SMEM_BYTES>>>(
            gah, gal, woh + (size_t)l * DM * DM, wol + (size_t)l * DM * DM,
            bo + l * DM, gx, gx, nullptr, nullptr, DM, DM, DM, DM);
        ln_bf_k<<<MTOK, 256>>>(gx, ghh, ghl, ln2_w + l * DM, ln2_b + l * DM);
        gemm_bf<1,false><<<grdF, 256, SMEM_BYTES>>>(
            ghh, ghl, w1h + (size_t)l * DM * FF, w1l + (size_t)l * DM * FF,
            b1 + l * FF, nullptr, nullptr, gfh, gfl, FF, DM, FF, FF);
        gemm_bf<2,false><<<grdD, 256, SMEM_BYTES>>>(
            gfh, gfl, w2h + (size_t)l * FF * DM, w2l + (size_t)l * FF * DM,
            b2 + l * DM, gx, gx, nullptr, nullptr, DM, FF, DM, DM);
    }

    ln_bf_k<<<MTOK, 256>>>(gx, ghh, ghl, lnf_w, lnf_b);
    // LM head: logits = h @ te_t  (te_t [D][VP] pre-transposed, zero-padded)
    gemm_bf<0,true><<<grdV, 256, SMEM_BYTES>>>(
        ghh, ghl, teh, tel, nullptr, nullptr, out, nullptr, nullptr,
        VV, DM, VP, VV);
}

// round 8
// speedup vs baseline: 2.6297x; 1.2011x over previous
#include <cuda_runtime.h>
#include <cuda_bf16.h>
#include <cuda_fp16.h>
#include <cstdint>
#include <math.h>

#define VV   50257
#define VP   50304            // V padded to multiple of 128
#define SS   1024
#define BBAT 2
#define DM   768
#define NH   12
#define HDIM 64
#define FF   3072
#define NL   2
#define MTOK (BBAT*SS)        // 2048
#define D3   (3*DM)           // 2304

typedef __nv_bfloat16 bf16;
typedef __half fp16;

// ---------------- persistent scratch (device globals) ----------------------
__device__ float g_x   [MTOK*DM];
__device__ float g_qkv [MTOK*D3];
__device__ bf16  g_hh  [MTOK*DM],  g_hl[MTOK*DM];
__device__ fp16  g_h16 [MTOK*DM];
__device__ bf16  g_ah  [MTOK*DM],  g_al[MTOK*DM];
__device__ bf16  g_fh  [MTOK*FF],  g_fl[MTOK*FF];
__device__ bf16  w_qkvh[NL*DM*D3], w_qkvl[NL*DM*D3];   // [l][k][n3]
__device__ bf16  w_oh  [NL*DM*DM], w_ol [NL*DM*DM];
__device__ bf16  w_1h  [NL*DM*FF], w_1l [NL*DM*FF];
__device__ bf16  w_2h  [NL*FF*DM], w_2l [NL*FF*DM];
__device__ fp16  g_te16[(size_t)DM*VP];                // [d][v] transposed fp16
__device__ float g_bqkv[NL*D3];

__device__ __forceinline__ void split_bf(float v, bf16& h, bf16& l) {
    h = __float2bfloat16_rn(v);
    l = __float2bfloat16_rn(v - __bfloat162float(h));
}
__device__ __forceinline__ float gelu_f(float z) {
    float z3 = z * z * z;
    return 0.5f * z * (1.0f + tanhf(0.7978845608028654f * (z + 0.044715f * z3)));
}

// ---------------- conversion kernels ---------------------------------------
__global__ void conv_split_k(const float* __restrict__ in, bf16* __restrict__ oh,
                             bf16* __restrict__ ol, int n) {
    int i = blockIdx.x * blockDim.x + threadIdx.x;
    if (i >= n) return;
    bf16 h, l; split_bf(in[i], h, l);
    oh[i] = h; ol[i] = l;
}

__global__ void conv_qkv_w_k(const float* __restrict__ wq, const float* __restrict__ wk,
                             const float* __restrict__ wv) {
    int i = blockIdx.x * blockDim.x + threadIdx.x;
    if (i >= NL * DM * D3) return;
    int l = i / (DM * D3);
    int r = i - l * DM * D3;
    int k = r / D3, n = r - k * D3;
    int which = n / DM, nn = n - which * DM;
    const float* src = (which == 0) ? wq : (which == 1) ? wk : wv;
    float v = src[(long)l * DM * DM + (long)k * DM + nn];
    bf16 h, lo; split_bf(v, h, lo);
    w_qkvh[i] = h; w_qkvl[i] = lo;
}

__global__ void pack_qkv_b_k(const float* __restrict__ bq, const float* __restrict__ bk,
                             const float* __restrict__ bv) {
    int i = blockIdx.x * blockDim.x + threadIdx.x;
    if (i >= NL * D3) return;
    int l = i / D3, n = i - l * D3;
    int which = n / DM, nn = n - which * DM;
    const float* src = (which == 0) ? bq : (which == 1) ? bk : bv;
    g_bqkv[i] = src[l * DM + nn];
}

// transpose tok_emb [V,D] -> [D][VP] fp16 (zero-pad v >= VV)
__global__ void conv_te_t16(const float* __restrict__ te) {
    __shared__ float t[32][33];
    int v0 = blockIdx.x * 32, d0 = blockIdx.y * 32;
    int tx = threadIdx.x, ty = threadIdx.y;   // 32 x 8
#pragma unroll
    for (int j = 0; j < 4; j++) {
        int v = v0 + ty + j * 8;
        t[ty + j * 8][tx] = (v < VV) ? te[(long)v * DM + d0 + tx] : 0.f;
    }
    __syncthreads();
#pragma unroll
    for (int j = 0; j < 4; j++) {
        int d = d0 + ty + j * 8;
        g_te16[(size_t)d * VP + v0 + tx] = __float2half_rn(t[tx][ty + j * 8]);
    }
}

// ---------------- embed ----------------------------------------------------
__global__ void embed_k(const int* __restrict__ idx,
                        const float* __restrict__ tok,
                        const float* __restrict__ pos) {
    int i = blockIdx.x * blockDim.x + threadIdx.x;
    if (i >= MTOK * DM) return;
    int m = i / DM, d = i % DM;
    int s = m % SS;
    int w = idx[m];
    g_x[i] = tok[(long)w * DM + d] + pos[s * DM + d];
}

// ---------------- layernorm variants ----------------------------------------
template <int OUT>   // 0: bf16 hi/lo, 1: fp16 single
__global__ void ln_k(const float* __restrict__ in, bf16* __restrict__ oh,
                     bf16* __restrict__ ol, fp16* __restrict__ o16,
                     const float* __restrict__ w, const float* __restrict__ b) {
    int row = blockIdx.x;
    const float* x = in + (long)row * DM;
    int tid = threadIdx.x;
    float s = 0.f, s2 = 0.f;
    for (int d = tid; d < DM; d += blockDim.x) {
        float v = x[d]; s += v; s2 += v * v;
    }
    __shared__ float rs[8], rs2[8], bc[2];
    for (int o = 16; o > 0; o >>= 1) {
        s  += __shfl_xor_sync(0xffffffffu, s,  o);
        s2 += __shfl_xor_sync(0xffffffffu, s2, o);
    }
    if ((tid & 31) == 0) { rs[tid >> 5] = s; rs2[tid >> 5] = s2; }
    __syncthreads();
    if (tid == 0) {
        float a = 0.f, a2 = 0.f;
        for (int i = 0; i < 8; i++) { a += rs[i]; a2 += rs2[i]; }
        float mean = a / DM;
        float var  = a2 / DM - mean * mean;
        bc[0] = mean; bc[1] = rsqrtf(var + 1e-5f);
    }
    __syncthreads();
    float mean = bc[0], inv = bc[1];
    for (int d = tid; d < DM; d += blockDim.x) {
        float v = (x[d] - mean) * inv * w[d] + b[d];
        if (OUT == 0) {
            bf16 h, l; split_bf(v, h, l);
            oh[(long)row * DM + d] = h;
            ol[(long)row * DM + d] = l;
        } else {
            o16[(long)row * DM + d] = __float2half_rn(v);
        }
    }
}

// ---------------- MMA helpers ----------------------------------------------
__device__ __forceinline__ void ldsm_x4(uint32_t* r, const void* p) {
    uint32_t a = (uint32_t)__cvta_generic_to_shared(p);
    asm volatile("ldmatrix.sync.aligned.m8n8.x4.shared.b16 {%0,%1,%2,%3}, [%4];"
                 : "=r"(r[0]), "=r"(r[1]), "=r"(r[2]), "=r"(r[3]) : "r"(a));
}
__device__ __forceinline__ void ldsm_x2_t(uint32_t* r, const void* p) {
    uint32_t a = (uint32_t)__cvta_generic_to_shared(p);
    asm volatile("ldmatrix.sync.aligned.m8n8.x2.trans.shared.b16 {%0,%1}, [%2];"
                 : "=r"(r[0]), "=r"(r[1]) : "r"(a));
}
__device__ __forceinline__ void mma_bf16(float* c, const uint32_t* a, const uint32_t* b) {
    asm volatile(
        "mma.sync.aligned.m16n8k16.row.col.f32.bf16.bf16.f32 "
        "{%0,%1,%2,%3}, {%4,%5,%6,%7}, {%8,%9}, {%0,%1,%2,%3};"
        : "+f"(c[0]), "+f"(c[1]), "+f"(c[2]), "+f"(c[3])
        : "r"(a[0]), "r"(a[1]), "r"(a[2]), "r"(a[3]), "r"(b[0]), "r"(b[1]));
}
__device__ __forceinline__ void mma_fp16(float* c, const uint32_t* a, const uint32_t* b) {
    asm volatile(
        "mma.sync.aligned.m16n8k16.row.col.f32.f16.f16.f32 "
        "{%0,%1,%2,%3}, {%4,%5,%6,%7}, {%8,%9}, {%0,%1,%2,%3};"
        : "+f"(c[0]), "+f"(c[1]), "+f"(c[2]), "+f"(c[3])
        : "r"(a[0]), "r"(a[1]), "r"(a[2]), "r"(a[3]), "r"(b[0]), "r"(b[1]));
}
__device__ __forceinline__ void cp16(void* dst, const void* src) {
    uint32_t d = (uint32_t)__cvta_generic_to_shared(dst);
    asm volatile("cp.async.cg.shared.global [%0], [%1], 16;" :: "r"(d), "l"(src));
}

// ================= bf16 hi/lo GEMM (layer GEMMs) — as R7 ====================
#define ASTR2 40
#define BSTR2 136
#define A_OFF 0
#define AL_OFF 5120
#define BH_OFF 10240
#define BL_OFF 14592
#define SSZ   18944
#define NSTAGE 3
#define SMEM_BYTES (NSTAGE*SSZ*2)

template <int EPI, bool NG>
__global__ __launch_bounds__(256, 2)
void gemm_bf(const bf16* __restrict__ Ah_g, const bf16* __restrict__ Al_g,
             const bf16* __restrict__ Bh_g, const bf16* __restrict__ Bl_g,
             const float* __restrict__ bias, const float* __restrict__ res,
             float* __restrict__ C, bf16* __restrict__ Ch, bf16* __restrict__ Cl,
             int Ndim, int Kdim, int ldb, int ldc) {
    extern __shared__ bf16 sm[];

    const int tid  = threadIdx.x;
    const int lane = tid & 31;
    const int wid  = tid >> 5;
    const int wm   = (wid >> 2) * 64;
    const int wn   = (wid & 3) * 32;
    const int a0   = blockIdx.y * 128;
    const int b0   = blockIdx.x * 128;
    const int niter = Kdim >> 5;

    float acc[4][4][4];
#pragma unroll
    for (int i = 0; i < 4; i++)
#pragma unroll
        for (int j = 0; j < 4; j++)
#pragma unroll
            for (int e = 0; e < 4; e++) acc[i][j][e] = 0.f;

    auto load_stage = [&](int buf, int k0) {
        bf16* s = sm + buf * SSZ;
#pragma unroll
        for (int i = 0; i < 2; i++) {
            int g = tid + i * 256;
            int r = g >> 2, c = (g & 3) * 8;
            cp16(&s[A_OFF  + r * ASTR2 + c], Ah_g + (size_t)(a0 + r) * Kdim + k0 + c);
            cp16(&s[AL_OFF + r * ASTR2 + c], Al_g + (size_t)(a0 + r) * Kdim + k0 + c);
        }
#pragma unroll
        for (int i = 0; i < 2; i++) {
            int g = tid + i * 256;
            int r = g >> 4, c = (g & 15) * 8;
            cp16(&s[BH_OFF + r * BSTR2 + c], Bh_g + (size_t)(k0 + r) * ldb + b0 + c);
            cp16(&s[BL_OFF + r * BSTR2 + c], Bl_g + (size_t)(k0 + r) * ldb + b0 + c);
        }
        asm volatile("cp.async.commit_group;");
    };

    load_stage(0, 0);
    load_stage(1, 32);

    for (int it = 0; it < niter; it++) {
        if (it + 1 < niter) asm volatile("cp.async.wait_group 1;");
        else                asm volatile("cp.async.wait_group 0;");
        __syncthreads();

        if (it + 2 < niter) load_stage((it + 2) % NSTAGE, (it + 2) << 5);

        bf16* s   = sm + (it % NSTAGE) * SSZ;
        bf16* sAh = s + A_OFF;
        bf16* sAl = s + AL_OFF;
        bf16* sBh = s + BH_OFF;
        bf16* sBl = s + BL_OFF;

#pragma unroll
        for (int ks = 0; ks < 2; ks++) {
            uint32_t ah[4][4], al[4][4], bh[4][2], bl[4][2];
            int arow = wm + (lane & 15);
            int acol = ks * 16 + (lane >> 4) * 8;
#pragma unroll
            for (int mt = 0; mt < 4; mt++) {
                ldsm_x4(ah[mt], &sAh[(arow + mt * 16) * ASTR2 + acol]);
                ldsm_x4(al[mt], &sAl[(arow + mt * 16) * ASTR2 + acol]);
            }
            int brow = ks * 16 + (lane & 15);
#pragma unroll
            for (int nt = 0; nt < 4; nt++) {
                ldsm_x2_t(bh[nt], &sBh[brow * BSTR2 + wn + nt * 8]);
                ldsm_x2_t(bl[nt], &sBl[brow * BSTR2 + wn + nt * 8]);
            }
#pragma unroll
            for (int mt = 0; mt < 4; mt++)
#pragma unroll
                for (int nt = 0; nt < 4; nt++) {
                    mma_bf16(acc[mt][nt], ah[mt], bh[nt]);
                    mma_bf16(acc[mt][nt], al[mt], bh[nt]);
                    mma_bf16(acc[mt][nt], ah[mt], bl[nt]);
                }
        }
    }

#pragma unroll
    for (int mt = 0; mt < 4; mt++) {
        long r0 = a0 + wm + mt * 16 + (lane >> 2);
        long r1 = r0 + 8;
#pragma unroll
        for (int nt = 0; nt < 4; nt++) {
            int cb = b0 + wn + nt * 8 + (lane & 3) * 2;
#pragma unroll
            for (int j = 0; j < 2; j++) {
                int col = cb + j;
                if (NG && col >= Ndim) continue;
                float v0 = acc[mt][nt][j];
                float v1 = acc[mt][nt][2 + j];
                if (bias) { float bb = bias[col]; v0 += bb; v1 += bb; }
                if (EPI == 1) {
                    v0 = gelu_f(v0); v1 = gelu_f(v1);
                    bf16 h0, l0, h1, l1;
                    split_bf(v0, h0, l0); split_bf(v1, h1, l1);
                    Ch[r0 * ldc + col] = h0; Cl[r0 * ldc + col] = l0;
                    Ch[r1 * ldc + col] = h1; Cl[r1 * ldc + col] = l1;
                } else {
                    if (EPI == 2) {
                        v0 += res[r0 * ldc + col];
                        v1 += res[r1 * ldc + col];
                    }
                    C[r0 * ldc + col] = v0;
                    C[r1 * ldc + col] = v1;
                }
            }
        }
    }
}

// ================= fp16 single-MMA GEMM (LM head) ===========================
// grid: (x = M tiles, y = N tiles) for B reuse across the wave.
#define FASTR 72              // A row stride (halves): 144B, conflict-free
#define FBSTR 136
#define FA_SZ (128*FASTR)     // 9216 halves
#define FB_SZ (64*FBSTR)      // 8704 halves
#define FSSZ  (FA_SZ + FB_SZ) // 17920 halves
#define FSMEM_BYTES (NSTAGE*FSSZ*2)   // 107520

__global__ __launch_bounds__(256, 2)
void gemm_fp16h(const fp16* __restrict__ Ag, const fp16* __restrict__ Bg,
                float* __restrict__ C, int Ndim, int Kdim, int ldb, int ldc) {
    extern __shared__ fp16 smh[];

    const int tid  = threadIdx.x;
    const int lane = tid & 31;
    const int wid  = tid >> 5;
    const int wm   = (wid >> 2) * 64;
    const int wn   = (wid & 3) * 32;
    const int a0   = blockIdx.x * 128;
    const int b0   = blockIdx.y * 128;
    const int niter = Kdim >> 6;      // 64-K stages

    float acc[4][4][4];
#pragma unroll
    for (int i = 0; i < 4; i++)
#pragma unroll
        for (int j = 0; j < 4; j++)
#pragma unroll
            for (int e = 0; e < 4; e++) acc[i][j][e] = 0.f;

    auto load_stage = [&](int buf, int k0) {
        fp16* s = smh + buf * FSSZ;
#pragma unroll
        for (int i = 0; i < 4; i++) {           // A: 128 x 64 = 1024 granules
            int g = tid + i * 256;
            int r = g >> 3, c = (g & 7) * 8;
            cp16(&s[r * FASTR + c], Ag + (size_t)(a0 + r) * Kdim + k0 + c);
        }
#pragma unroll
        for (int i = 0; i < 4; i++) {           // B: 64 x 128 = 1024 granules
            int g = tid + i * 256;
            int r = g >> 4, c = (g & 15) * 8;
            cp16(&s[FA_SZ + r * FBSTR + c], Bg + (size_t)(k0 + r) * ldb + b0 + c);
        }
        asm volatile("cp.async.commit_group;");
    };

    load_stage(0, 0);
    load_stage(1, 64);

    for (int it = 0; it < niter; it++) {
        if (it + 1 < niter) asm volatile("cp.async.wait_group 1;");
        else                asm volatile("cp.async.wait_group 0;");
        __syncthreads();

        if (it + 2 < niter) load_stage((it + 2) % NSTAGE, (it + 2) << 6);

        fp16* sA = smh + (it % NSTAGE) * FSSZ;
        fp16* sB = sA + FA_SZ;

#pragma unroll
        for (int ks = 0; ks < 4; ks++) {
            uint32_t ah[4][4], bh[4][2];
            int arow = wm + (lane & 15);
            int acol = ks * 16 + (lane >> 4) * 8;
#pragma unroll
            for (int mt = 0; mt < 4; mt++)
                ldsm_x4(ah[mt], &sA[(arow + mt * 16) * FASTR + acol]);
            int brow = ks * 16 + (lane & 15);
#pragma unroll
            for (int nt = 0; nt < 4; nt++)
                ldsm_x2_t(bh[nt], &sB[brow * FBSTR + wn + nt * 8]);
#pragma unroll
            for (int mt = 0; mt < 4; mt++)
#pragma unroll
                for (int nt = 0; nt < 4; nt++)
                    mma_fp16(acc[mt][nt], ah[mt], bh[nt]);
        }
    }

#pragma unroll
    for (int mt = 0; mt < 4; mt++) {
        long r0 = a0 + wm + mt * 16 + (lane >> 2);
        long r1 = r0 + 8;
#pragma unroll
        for (int nt = 0; nt < 4; nt++) {
            int cb = b0 + wn + nt * 8 + (lane & 3) * 2;
#pragma unroll
            for (int j = 0; j < 2; j++) {
                int col = cb + j;
                if (col >= Ndim) continue;
                C[r0 * ldc + col] = acc[mt][nt][j];
                C[r1 * ldc + col] = acc[mt][nt][2 + j];
            }
        }
    }
}

// ---------------- causal attention: one block per (q, h, b) ----------------
__global__ __launch_bounds__(128)
void attn_k() {
    int q = blockIdx.x, h = blockIdx.y, b = blockIdx.z;
    int tid = threadIdx.x;
    int m0 = b * SS;

    __shared__ float qs[HDIM];
    __shared__ float sc[SS];
    __shared__ float rbuf[5];
    __shared__ float part[128];

    const float* qp = g_qkv + (long)(m0 + q) * D3 + h * HDIM;
    if (tid < HDIM) qs[tid] = qp[tid];
    __syncthreads();

    int nk = q + 1;
    float lmax = -1e30f;
    for (int j = tid; j < nk; j += 128) {
        const float4* kp = (const float4*)(g_qkv + (long)(m0 + j) * D3 + DM + h * HDIM);
        float s = 0.f;
#pragma unroll
        for (int d4 = 0; d4 < HDIM / 4; d4++) {
            float4 kv = kp[d4];
            s += qs[d4 * 4 + 0] * kv.x + qs[d4 * 4 + 1] * kv.y
               + qs[d4 * 4 + 2] * kv.z + qs[d4 * 4 + 3] * kv.w;
        }
        s *= 0.125f;
        sc[j] = s;
        lmax = fmaxf(lmax, s);
    }
    for (int o = 16; o > 0; o >>= 1) lmax = fmaxf(lmax, __shfl_xor_sync(0xffffffffu, lmax, o));
    if ((tid & 31) == 0) rbuf[tid >> 5] = lmax;
    __syncthreads();
    if (tid == 0) {
        float m = fmaxf(fmaxf(rbuf[0], rbuf[1]), fmaxf(rbuf[2], rbuf[3]));
        rbuf[4] = m;
    }
    __syncthreads();
    float smax = rbuf[4];
    __syncthreads();

    float lsum = 0.f;
    for (int j = tid; j < nk; j += 128) {
        float e = __expf(sc[j] - smax);
        sc[j] = e;
        lsum += e;
    }
    for (int o = 16; o > 0; o >>= 1) lsum += __shfl_xor_sync(0xffffffffu, lsum, o);
    if ((tid & 31) == 0) rbuf[tid >> 5] = lsum;
    __syncthreads();
    if (tid == 0) rbuf[4] = 1.0f / (rbuf[0] + rbuf[1] + rbuf[2] + rbuf[3]);
    __syncthreads();
    float inv = rbuf[4];

    int d = tid & 63;
    int hv = tid >> 6;
    float acc = 0.f;
    for (int j = hv; j < nk; j += 2)
        acc += sc[j] * g_qkv[(long)(m0 + j) * D3 + 2 * DM + h * HDIM + d];
    part[tid] = acc;
    __syncthreads();
    if (tid < 64) {
        float o = (part[tid] + part[tid + 64]) * inv;
        bf16 hh, ll; split_bf(o, hh, ll);
        long idx = (long)(m0 + q) * DM + h * HDIM + tid;
        g_ah[idx] = hh; g_al[idx] = ll;
    }
}

// ---------------- host orchestration ---------------------------------------
extern "C" void kernel_launch(void* const* d_in, const int* in_sizes, int n_in,
                              void* d_out, int out_size) {
    const int*   word_idx = (const int*)  d_in[0];
    const float* tok_emb  = (const float*)d_in[1];
    const float* pos_emb  = (const float*)d_in[2];
    const float* ln1_w    = (const float*)d_in[3];
    const float* ln1_b    = (const float*)d_in[4];
    const float* wq       = (const float*)d_in[5];
    const float* bq       = (const float*)d_in[6];
    const float* wk       = (const float*)d_in[7];
    const float* bk       = (const float*)d_in[8];
    const float* wv       = (const float*)d_in[9];
    const float* bv       = (const float*)d_in[10];
    const float* wo       = (const float*)d_in[11];
    const float* bo       = (const float*)d_in[12];
    const float* ln2_w    = (const float*)d_in[13];
    const float* ln2_b    = (const float*)d_in[14];
    const float* w1       = (const float*)d_in[15];
    const float* b1       = (const float*)d_in[16];
    const float* w2       = (const float*)d_in[17];
    const float* b2       = (const float*)d_in[18];
    const float* lnf_w    = (const float*)d_in[19];
    const float* lnf_b    = (const float*)d_in[20];
    float* out = (float*)d_out;

    float *gx, *gqkv, *gbq;
    bf16 *ghh, *ghl, *gah, *gal, *gfh, *gfl;
    bf16 *wqkvh, *wqkvl, *woh, *wol, *w1h, *w1l, *w2h, *w2l;
    fp16 *gh16, *te16;
    cudaGetSymbolAddress((void**)&gx,    g_x);
    cudaGetSymbolAddress((void**)&gqkv,  g_qkv);
    cudaGetSymbolAddress((void**)&gbq,   g_bqkv);
    cudaGetSymbolAddress((void**)&ghh,   g_hh);
    cudaGetSymbolAddress((void**)&ghl,   g_hl);
    cudaGetSymbolAddress((void**)&gh16,  g_h16);
    cudaGetSymbolAddress((void**)&gah,   g_ah);
    cudaGetSymbolAddress((void**)&gal,   g_al);
    cudaGetSymbolAddress((void**)&gfh,   g_fh);
    cudaGetSymbolAddress((void**)&gfl,   g_fl);
    cudaGetSymbolAddress((void**)&wqkvh, w_qkvh);
    cudaGetSymbolAddress((void**)&wqkvl, w_qkvl);
    cudaGetSymbolAddress((void**)&woh,   w_oh);
    cudaGetSymbolAddress((void**)&wol,   w_ol);
    cudaGetSymbolAddress((void**)&w1h,   w_1h);
    cudaGetSymbolAddress((void**)&w1l,   w_1l);
    cudaGetSymbolAddress((void**)&w2h,   w_2h);
    cudaGetSymbolAddress((void**)&w2l,   w_2l);
    cudaGetSymbolAddress((void**)&te16,  g_te16);

    cudaFuncSetAttribute(gemm_bf<0,false>, cudaFuncAttributeMaxDynamicSharedMemorySize, SMEM_BYTES);
    cudaFuncSetAttribute(gemm_bf<1,false>, cudaFuncAttributeMaxDynamicSharedMemorySize, SMEM_BYTES);
    cudaFuncSetAttribute(gemm_bf<2,false>, cudaFuncAttributeMaxDynamicSharedMemorySize, SMEM_BYTES);
    cudaFuncSetAttribute(gemm_fp16h,       cudaFuncAttributeMaxDynamicSharedMemorySize, FSMEM_BYTES);

    // ---- one-time conversions ----
    conv_qkv_w_k<<<(NL * DM * D3 + 255) / 256, 256>>>(wq, wk, wv);
    pack_qkv_b_k<<<(NL * D3 + 255) / 256, 256>>>(bq, bk, bv);
    conv_split_k<<<(NL * DM * DM + 255) / 256, 256>>>(wo, woh, wol, NL * DM * DM);
    conv_split_k<<<(NL * DM * FF + 255) / 256, 256>>>(w1, w1h, w1l, NL * DM * FF);
    conv_split_k<<<(NL * FF * DM + 255) / 256, 256>>>(w2, w2h, w2l, NL * FF * DM);
    conv_te_t16<<<dim3(VP / 32, DM / 32), dim3(32, 8)>>>(tok_emb);

    embed_k<<<(MTOK * DM + 255) / 256, 256>>>(word_idx, tok_emb, pos_emb);

    dim3 grdQKV(D3 / 128, MTOK / 128);
    dim3 grdD  (DM / 128, MTOK / 128);
    dim3 grdF  (FF / 128, MTOK / 128);
    dim3 grdV  (MTOK / 128, VP / 128);   // x = M tiles (16), y = N tiles (393)

    for (int l = 0; l < NL; l++) {
        ln_k<0><<<MTOK, 256>>>(gx, ghh, ghl, nullptr, ln1_w + l * DM, ln1_b + l * DM);
        gemm_bf<0,false><<<grdQKV, 256, SMEM_BYTES>>>(
            ghh, ghl, wqkvh + (size_t)l * DM * D3, wqkvl + (size_t)l * DM * D3,
            gbq + l * D3, nullptr, gqkv, nullptr, nullptr, D3, DM, D3, D3);
        attn_k<<<dim3(SS, NH, BBAT), 128>>>();
        gemm_bf<2,false><<<grdD, 256, SMEM_BYTES>>>(
            gah, gal, woh + (size_t)l * DM * DM, wol + (size_t)l * DM * DM,
            bo + l * DM, gx, gx, nullptr, nullptr, DM, DM, DM, DM);
        ln_k<0><<<MTOK, 256>>>(gx, ghh, ghl, nullptr, ln2_w + l * DM, ln2_b + l * DM);
        gemm_bf<1,false><<<grdF, 256, SMEM_BYTES>>>(
            ghh, ghl, w1h + (size_t)l * DM * FF, w1l + (size_t)l * DM * FF,
            b1 + l * FF, nullptr, nullptr, gfh, gfl, FF, DM, FF, FF);
        gemm_bf<2,false><<<grdD, 256, SMEM_BYTES>>>(
            gfh, gfl, w2h + (size_t)l * FF * DM, w2l + (size_t)l * FF * DM,
            b2 + l * DM, gx, gx, nullptr, nullptr, DM, FF, DM, DM);
    }

    ln_k<1><<<MTOK, 256>>>(gx, nullptr, nullptr, gh16, lnf_w, lnf_b);
    // LM head: logits = h16 @ te16  (fp16 single-MMA; te16 [D][VP], zero-padded)
    gemm_fp16h<<<grdV, 256, FSMEM_BYTES>>>(gh16, te16, out, VV, DM, VP, VV);
}

// round 9
// speedup vs baseline: 3.5529x; 1.3511x over previous
#include <cuda_runtime.h>
#include <cuda_fp16.h>
#include <cstdint>
#include <math.h>

#define VV   50257
#define VP   50304
#define SS   1024
#define BBAT 2
#define DM   768
#define NH   12
#define HDIM 64
#define FF   3072
#define NL   2
#define MTOK (BBAT*SS)
#define D3   (3*DM)

typedef __half fp16;

// ---------------- persistent scratch ---------------------------------------
__device__ float g_x   [MTOK*DM];
__device__ float g_qkv [MTOK*D3];
__device__ fp16  g_h16 [MTOK*DM];
__device__ fp16  g_a16 [MTOK*DM];
__device__ fp16  g_f16 [MTOK*FF];
__device__ fp16  w_qkv16[NL*DM*D3];          // [l][k][n3]
__device__ fp16  w_o16 [NL*DM*DM];           // [k][n]
__device__ fp16  w_116 [NL*DM*FF];
__device__ fp16  w_216 [NL*FF*DM];
__device__ fp16  g_te16[(size_t)DM*VP];      // [d][v] transposed, padded
__device__ float g_bqkv[NL*D3];

__device__ __forceinline__ float gelu_f(float z) {
    float z3 = z * z * z;
    return 0.5f * z * (1.0f + tanhf(0.7978845608028654f * (z + 0.044715f * z3)));
}

// ---------------- conversions ----------------------------------------------
__global__ void conv16_k(const float* __restrict__ in, fp16* __restrict__ o, int n) {
    int i = blockIdx.x * blockDim.x + threadIdx.x;
    if (i < n) o[i] = __float2half_rn(in[i]);
}

__global__ void conv_qkv_w16(const float* __restrict__ wq, const float* __restrict__ wk,
                             const float* __restrict__ wv) {
    int i = blockIdx.x * blockDim.x + threadIdx.x;
    if (i >= NL * DM * D3) return;
    int l = i / (DM * D3);
    int r = i - l * DM * D3;
    int k = r / D3, n = r - k * D3;
    int which = n / DM, nn = n - which * DM;
    const float* src = (which == 0) ? wq : (which == 1) ? wk : wv;
    w_qkv16[i] = __float2half_rn(src[(long)l * DM * DM + (long)k * DM + nn]);
}

__global__ void pack_qkv_b_k(const float* __restrict__ bq, const float* __restrict__ bk,
                             const float* __restrict__ bv) {
    int i = blockIdx.x * blockDim.x + threadIdx.x;
    if (i >= NL * D3) return;
    int l = i / D3, n = i - l * D3;
    int which = n / DM, nn = n - which * DM;
    const float* src = (which == 0) ? bq : (which == 1) ? bk : bv;
    g_bqkv[i] = src[l * DM + nn];
}

__global__ void conv_te_t16(const float* __restrict__ te) {
    __shared__ float t[32][33];
    int v0 = blockIdx.x * 32, d0 = blockIdx.y * 32;
    int tx = threadIdx.x, ty = threadIdx.y;   // 32 x 8
#pragma unroll
    for (int j = 0; j < 4; j++) {
        int v = v0 + ty + j * 8;
        t[ty + j * 8][tx] = (v < VV) ? te[(long)v * DM + d0 + tx] : 0.f;
    }
    __syncthreads();
#pragma unroll
    for (int j = 0; j < 4; j++) {
        int d = d0 + ty + j * 8;
        g_te16[(size_t)d * VP + v0 + tx] = __float2half_rn(t[tx][ty + j * 8]);
    }
}

// ---------------- embed ----------------------------------------------------
__global__ void embed_k(const int* __restrict__ idx,
                        const float* __restrict__ tok,
                        const float* __restrict__ pos) {
    int i = blockIdx.x * blockDim.x + threadIdx.x;
    if (i >= MTOK * DM) return;
    int m = i / DM, d = i % DM;
    int s = m % SS;
    int w = idx[m];
    g_x[i] = tok[(long)w * DM + d] + pos[s * DM + d];
}

// ---------------- layernorm -> fp16 -----------------------------------------
__global__ void ln16_k(const float* __restrict__ in, fp16* __restrict__ o16,
                       const float* __restrict__ w, const float* __restrict__ b) {
    int row = blockIdx.x;
    const float* x = in + (long)row * DM;
    int tid = threadIdx.x;
    float s = 0.f, s2 = 0.f;
    for (int d = tid; d < DM; d += blockDim.x) {
        float v = x[d]; s += v; s2 += v * v;
    }
    __shared__ float rs[8], rs2[8], bc[2];
    for (int o = 16; o > 0; o >>= 1) {
        s  += __shfl_xor_sync(0xffffffffu, s,  o);
        s2 += __shfl_xor_sync(0xffffffffu, s2, o);
    }
    if ((tid & 31) == 0) { rs[tid >> 5] = s; rs2[tid >> 5] = s2; }
    __syncthreads();
    if (tid == 0) {
        float a = 0.f, a2 = 0.f;
        for (int i = 0; i < 8; i++) { a += rs[i]; a2 += rs2[i]; }
        float mean = a / DM;
        float var  = a2 / DM - mean * mean;
        bc[0] = mean; bc[1] = rsqrtf(var + 1e-5f);
    }
    __syncthreads();
    float mean = bc[0], inv = bc[1];
    for (int d = tid; d < DM; d += blockDim.x) {
        float v = (x[d] - mean) * inv * w[d] + b[d];
        o16[(long)row * DM + d] = __float2half_rn(v);
    }
}

// ---------------- MMA helpers ----------------------------------------------
__device__ __forceinline__ void ldsm_x4(uint32_t* r, const void* p) {
    uint32_t a = (uint32_t)__cvta_generic_to_shared(p);
    asm volatile("ldmatrix.sync.aligned.m8n8.x4.shared.b16 {%0,%1,%2,%3}, [%4];"
                 : "=r"(r[0]), "=r"(r[1]), "=r"(r[2]), "=r"(r[3]) : "r"(a));
}
__device__ __forceinline__ void ldsm_x2_t(uint32_t* r, const void* p) {
    uint32_t a = (uint32_t)__cvta_generic_to_shared(p);
    asm volatile("ldmatrix.sync.aligned.m8n8.x2.trans.shared.b16 {%0,%1}, [%2];"
                 : "=r"(r[0]), "=r"(r[1]) : "r"(a));
}
__device__ __forceinline__ void mma_fp16(float* c, const uint32_t* a, const uint32_t* b) {
    asm volatile(
        "mma.sync.aligned.m16n8k16.row.col.f32.f16.f16.f32 "
        "{%0,%1,%2,%3}, {%4,%5,%6,%7}, {%8,%9}, {%0,%1,%2,%3};"
        : "+f"(c[0]), "+f"(c[1]), "+f"(c[2]), "+f"(c[3])
        : "r"(a[0]), "r"(a[1]), "r"(a[2]), "r"(a[3]), "r"(b[0]), "r"(b[1]));
}
__device__ __forceinline__ void cp16(void* dst, const void* src) {
    uint32_t d = (uint32_t)__cvta_generic_to_shared(dst);
    asm volatile("cp.async.cg.shared.global [%0], [%1], 16;" :: "r"(d), "l"(src));
}

// ================= fp16 single-MMA GEMM =====================================
#define FASTR 72
#define FBSTR 136
#define FA_SZ (128*FASTR)
#define FB_SZ (64*FBSTR)
#define FSSZ  (FA_SZ + FB_SZ)
#define NSTAGE 3
#define FSMEM_BYTES (NSTAGE*FSSZ*2)

// EPI: 0 = fp32 out (+bias opt), 1 = gelu(acc+bias) -> fp16, 2 = bias+res fp32
// NG : guard N on epilogue; XM : blockIdx.x is the M dimension
template <int EPI, bool NG, bool XM>
__global__ __launch_bounds__(256, 2)
void gemm_f16(const fp16* __restrict__ Ag, const fp16* __restrict__ Bg,
              const float* __restrict__ bias, const float* __restrict__ res,
              float* __restrict__ C, fp16* __restrict__ C16,
              int Ndim, int Kdim, int ldb, int ldc) {
    extern __shared__ fp16 smh[];

    const int tid  = threadIdx.x;
    const int lane = tid & 31;
    const int wid  = tid >> 5;
    const int wm   = (wid >> 2) * 64;
    const int wn   = (wid & 3) * 32;
    const int a0   = (XM ? blockIdx.x : blockIdx.y) * 128;
    const int b0   = (XM ? blockIdx.y : blockIdx.x) * 128;
    const int niter = Kdim >> 6;

    float acc[4][4][4];
#pragma unroll
    for (int i = 0; i < 4; i++)
#pragma unroll
        for (int j = 0; j < 4; j++)
#pragma unroll
            for (int e = 0; e < 4; e++) acc[i][j][e] = 0.f;

    auto load_stage = [&](int buf, int k0) {
        fp16* s = smh + buf * FSSZ;
#pragma unroll
        for (int i = 0; i < 4; i++) {
            int g = tid + i * 256;
            int r = g >> 3, c = (g & 7) * 8;
            cp16(&s[r * FASTR + c], Ag + (size_t)(a0 + r) * Kdim + k0 + c);
        }
#pragma unroll
        for (int i = 0; i < 4; i++) {
            int g = tid + i * 256;
            int r = g >> 4, c = (g & 15) * 8;
            cp16(&s[FA_SZ + r * FBSTR + c], Bg + (size_t)(k0 + r) * ldb + b0 + c);
        }
        asm volatile("cp.async.commit_group;");
    };

    load_stage(0, 0);
    load_stage(1, 64);

    for (int it = 0; it < niter; it++) {
        if (it + 1 < niter) asm volatile("cp.async.wait_group 1;");
        else                asm volatile("cp.async.wait_group 0;");
        __syncthreads();

        if (it + 2 < niter) load_stage((it + 2) % NSTAGE, (it + 2) << 6);

        fp16* sA = smh + (it % NSTAGE) * FSSZ;
        fp16* sB = sA + FA_SZ;

#pragma unroll
        for (int ks = 0; ks < 4; ks++) {
            uint32_t ah[4][4], bh[4][2];
            int arow = wm + (lane & 15);
            int acol = ks * 16 + (lane >> 4) * 8;
#pragma unroll
            for (int mt = 0; mt < 4; mt++)
                ldsm_x4(ah[mt], &sA[(arow + mt * 16) * FASTR + acol]);
            int brow = ks * 16 + (lane & 15);
#pragma unroll
            for (int nt = 0; nt < 4; nt++)
                ldsm_x2_t(bh[nt], &sB[brow * FBSTR + wn + nt * 8]);
#pragma unroll
            for (int mt = 0; mt < 4; mt++)
#pragma unroll
                for (int nt = 0; nt < 4; nt++)
                    mma_fp16(acc[mt][nt], ah[mt], bh[nt]);
        }
    }

#pragma unroll
    for (int mt = 0; mt < 4; mt++) {
        long r0 = a0 + wm + mt * 16 + (lane >> 2);
        long r1 = r0 + 8;
#pragma unroll
        for (int nt = 0; nt < 4; nt++) {
            int cb = b0 + wn + nt * 8 + (lane & 3) * 2;
#pragma unroll
            for (int j = 0; j < 2; j++) {
                int col = cb + j;
                if (NG && col >= Ndim) continue;
                float v0 = acc[mt][nt][j];
                float v1 = acc[mt][nt][2 + j];
                if (bias) { float bb = bias[col]; v0 += bb; v1 += bb; }
                if (EPI == 1) {
                    C16[r0 * ldc + col] = __float2half_rn(gelu_f(v0));
                    C16[r1 * ldc + col] = __float2half_rn(gelu_f(v1));
                } else {
                    if (EPI == 2) {
                        v0 += res[r0 * ldc + col];
                        v1 += res[r1 * ldc + col];
                    }
                    C[r0 * ldc + col] = v0;
                    C[r1 * ldc + col] = v1;
                }
            }
        }
    }
}

// ---------------- tiled causal attention ------------------------------------
// block = (q-tile of 64, head, batch); 256 threads = 64 q-rows x 4 (p).
// Each thread owns 16 head-dims of its q row; online softmax across 64-key tiles.
#define AT_SMEM ((64*64 + 64*64 + 64*65) * 4)   // Ks, Vs, sc  = 49408 B

__global__ __launch_bounds__(256)
void attn_t() {
    extern __shared__ float ash[];
    float* Ks = ash;                 // [64][64]
    float* Vs = ash + 64 * 64;       // [64][64]
    float* sc = ash + 2 * 64 * 64;   // [64][65]

    const int tid = threadIdx.x;
    const int q   = tid >> 2;        // 0..63
    const int p   = tid & 3;         // 0..3
    const int q0  = blockIdx.x * 64;
    const int h   = blockIdx.y;
    const int b   = blockIdx.z;
    const int m0  = b * SS;
    const int qg  = q0 + q;          // sequence position of my q row

    // load my q slice (16 dims) into regs
    float qreg[16];
    {
        const float4* qp = (const float4*)(g_qkv + (size_t)(m0 + qg) * D3 + h * HDIM + p * 16);
#pragma unroll
        for (int i = 0; i < 4; i++) {
            float4 v = qp[i];
            qreg[i*4+0] = v.x; qreg[i*4+1] = v.y; qreg[i*4+2] = v.z; qreg[i*4+3] = v.w;
        }
    }

    float o[16];
#pragma unroll
    for (int i = 0; i < 16; i++) o[i] = 0.f;
    float m_run = -1e30f, s_run = 0.f;

    const int ntile = blockIdx.x + 1;
    for (int t = 0; t < ntile; t++) {
        int j0 = t * 64;
        __syncthreads();   // protect previous tile's readers
        // load K,V tiles (64 rows x 64 dims, float4)
#pragma unroll
        for (int i = 0; i < 4; i++) {
            int g = tid + i * 256;            // 1024 float4 slots
            int r = g >> 4, c4 = (g & 15);
            const float* kr = g_qkv + (size_t)(m0 + j0 + r) * D3 + DM + h * HDIM;
            const float* vr = kr + DM;
            ((float4*)(Ks + r * 64))[c4] = ((const float4*)kr)[c4];
            ((float4*)(Vs + r * 64))[c4] = ((const float4*)vr)[c4];
        }
        __syncthreads();

        // pass 1: scores (quad partial-dot + shfl reduce)
        for (int j = 0; j < 64; j++) {
            const float4* kp = (const float4*)(Ks + j * 64 + p * 16);
            float prt = 0.f;
#pragma unroll
            for (int i = 0; i < 4; i++) {
                float4 kv = kp[i];
                prt += qreg[i*4+0]*kv.x + qreg[i*4+1]*kv.y
                     + qreg[i*4+2]*kv.z + qreg[i*4+3]*kv.w;
            }
            prt += __shfl_xor_sync(0xffffffffu, prt, 1);
            prt += __shfl_xor_sync(0xffffffffu, prt, 2);
            if (p == (j & 3)) sc[q * 65 + j] = prt * 0.125f;
        }
        __syncwarp();

        // pass 2: tile max, exp, sum (each thread owns j in [p*16, p*16+16))
        float se[16];
        float lmax = -1e30f;
#pragma unroll
        for (int jj = 0; jj < 16; jj++) {
            int j = p * 16 + jj;
            se[jj] = sc[q * 65 + j];
            if (j0 + j <= qg) lmax = fmaxf(lmax, se[jj]);
        }
        lmax = fmaxf(lmax, __shfl_xor_sync(0xffffffffu, lmax, 1));
        lmax = fmaxf(lmax, __shfl_xor_sync(0xffffffffu, lmax, 2));
        float m_new = fmaxf(m_run, lmax);
        float corr  = __expf(m_run - m_new);
        float lsum = 0.f;
#pragma unroll
        for (int jj = 0; jj < 16; jj++) {
            int j = p * 16 + jj;
            float e = (j0 + j <= qg) ? __expf(se[jj] - m_new) : 0.f;
            sc[q * 65 + j] = e;
            lsum += e;
        }
        lsum += __shfl_xor_sync(0xffffffffu, lsum, 1);
        lsum += __shfl_xor_sync(0xffffffffu, lsum, 2);
        s_run = s_run * corr + lsum;
        m_run = m_new;
#pragma unroll
        for (int i = 0; i < 16; i++) o[i] *= corr;
        __syncwarp();

        // pass 3: V accumulation over all 64 keys
        for (int j = 0; j < 64; j++) {
            float e = sc[q * 65 + j];
            const float4* vp = (const float4*)(Vs + j * 64 + p * 16);
#pragma unroll
            for (int i = 0; i < 4; i++) {
                float4 vv = vp[i];
                o[i*4+0] += e * vv.x; o[i*4+1] += e * vv.y;
                o[i*4+2] += e * vv.z; o[i*4+3] += e * vv.w;
            }
        }
    }

    float invs = 1.0f / s_run;
    fp16* op = g_a16 + (size_t)(m0 + qg) * DM + h * HDIM + p * 16;
#pragma unroll
    for (int i = 0; i < 16; i++) op[i] = __float2half_rn(o[i] * invs);
}

// ---------------- host orchestration ----------------------------------------
extern "C" void kernel_launch(void* const* d_in, const int* in_sizes, int n_in,
                              void* d_out, int out_size) {
    const int*   word_idx = (const int*)  d_in[0];
    const float* tok_emb  = (const float*)d_in[1];
    const float* pos_emb  = (const float*)d_in[2];
    const float* ln1_w    = (const float*)d_in[3];
    const float* ln1_b    = (const float*)d_in[4];
    const float* wq       = (const float*)d_in[5];
    const float* bq       = (const float*)d_in[6];
    const float* wk       = (const float*)d_in[7];
    const float* bk       = (const float*)d_in[8];
    const float* wv       = (const float*)d_in[9];
    const float* bv       = (const float*)d_in[10];
    const float* wo       = (const float*)d_in[11];
    const float* bo       = (const float*)d_in[12];
    const float* ln2_w    = (const float*)d_in[13];
    const float* ln2_b    = (const float*)d_in[14];
    const float* w1       = (const float*)d_in[15];
    const float* b1       = (const float*)d_in[16];
    const float* w2       = (const float*)d_in[17];
    const float* b2       = (const float*)d_in[18];
    const float* lnf_w    = (const float*)d_in[19];
    const float* lnf_b    = (const float*)d_in[20];
    float* out = (float*)d_out;

    float *gx, *gqkv, *gbq;
    fp16 *gh16, *ga16, *gf16, *wqkv16, *wo16, *w116, *w216, *te16;
    cudaGetSymbolAddress((void**)&gx,     g_x);
    cudaGetSymbolAddress((void**)&gqkv,   g_qkv);
    cudaGetSymbolAddress((void**)&gbq,    g_bqkv);
    cudaGetSymbolAddress((void**)&gh16,   g_h16);
    cudaGetSymbolAddress((void**)&ga16,   g_a16);
    cudaGetSymbolAddress((void**)&gf16,   g_f16);
    cudaGetSymbolAddress((void**)&wqkv16, w_qkv16);
    cudaGetSymbolAddress((void**)&wo16,   w_o16);
    cudaGetSymbolAddress((void**)&w116,   w_116);
    cudaGetSymbolAddress((void**)&w216,   w_216);
    cudaGetSymbolAddress((void**)&te16,   g_te16);

    cudaFuncSetAttribute(gemm_f16<0,false,false>, cudaFuncAttributeMaxDynamicSharedMemorySize, FSMEM_BYTES);
    cudaFuncSetAttribute(gemm_f16<1,false,false>, cudaFuncAttributeMaxDynamicSharedMemorySize, FSMEM_BYTES);
    cudaFuncSetAttribute(gemm_f16<2,false,false>, cudaFuncAttributeMaxDynamicSharedMemorySize, FSMEM_BYTES);
    cudaFuncSetAttribute(gemm_f16<0,true,true>,   cudaFuncAttributeMaxDynamicSharedMemorySize, FSMEM_BYTES);
    cudaFuncSetAttribute(attn_t, cudaFuncAttributeMaxDynamicSharedMemorySize, AT_SMEM);

    // ---- one-time conversions ----
    conv_qkv_w16<<<(NL * DM * D3 + 255) / 256, 256>>>(wq, wk, wv);
    pack_qkv_b_k<<<(NL * D3 + 255) / 256, 256>>>(bq, bk, bv);
    conv16_k<<<(NL * DM * DM + 255) / 256, 256>>>(wo, wo16, NL * DM * DM);
    conv16_k<<<(NL * DM * FF + 255) / 256, 256>>>(w1, w116, NL * DM * FF);
    conv16_k<<<(NL * FF * DM + 255) / 256, 256>>>(w2, w216, NL * FF * DM);
    conv_te_t16<<<dim3(VP / 32, DM / 32), dim3(32, 8)>>>(tok_emb);

    embed_k<<<(MTOK * DM + 255) / 256, 256>>>(word_idx, tok_emb, pos_emb);

    dim3 grdQKV(D3 / 128, MTOK / 128);   // 18 x 16
    dim3 grdD  (DM / 128, MTOK / 128);   // 6 x 16
    dim3 grdF  (FF / 128, MTOK / 128);   // 24 x 16
    dim3 grdV  (MTOK / 128, VP / 128);   // 16 x 393
    dim3 grdA  (SS / 64, NH, BBAT);      // 16 x 12 x 2

    for (int l = 0; l < NL; l++) {
        ln16_k<<<MTOK, 256>>>(gx, gh16, ln1_w + l * DM, ln1_b + l * DM);
        gemm_f16<0,false,false><<<grdQKV, 256, FSMEM_BYTES>>>(
            gh16, wqkv16 + (size_t)l * DM * D3, gbq + l * D3, nullptr,
            gqkv, nullptr, D3, DM, D3, D3);
        attn_t<<<grdA, 256, AT_SMEM>>>();
        gemm_f16<2,false,false><<<grdD, 256, FSMEM_BYTES>>>(
            ga16, wo16 + (size_t)l * DM * DM, bo + l * DM, gx,
            gx, nullptr, DM, DM, DM, DM);
        ln16_k<<<MTOK, 256>>>(gx, gh16, ln2_w + l * DM, ln2_b + l * DM);
        gemm_f16<1,false,false><<<grdF, 256, FSMEM_BYTES>>>(
            gh16, w116 + (size_t)l * DM * FF, b1 + l * FF, nullptr,
            nullptr, gf16, FF, DM, FF, FF);
        gemm_f16<2,false,false><<<grdD, 256, FSMEM_BYTES>>>(
            gf16, w216 + (size_t)l * FF * DM, b2 + l * DM, gx,
            gx, nullptr, DM, FF, DM, DM);
    }

    ln16_k<<<MTOK, 256>>>(gx, gh16, lnf_w, lnf_b);
    gemm_f16<0,true,true><<<grdV, 256, FSMEM_BYTES>>>(
        gh16, te16, nullptr, nullptr, out, nullptr, VV, DM, VP, VV);
}